// round 1
// baseline (speedup 1.0000x reference)
#include <cuda_runtime.h>
#include <cstdint>

// ---------------------------------------------------------------------------
// Problem constants
//   x     : [4,900,4,32,64]  f32   (B,Q,G,P=IN_POINTS,C=EFF_IN)
//   query : [4,900,256]      f32
//   Wp    : [256, 32768]     f32
//   bp    : [32768]          f32
//   Wo    : [32768, 256]     f32
//   bo    : [256]            f32
//   out   : [4,900,256]      f32
// ---------------------------------------------------------------------------
#define NTOK   3600
#define QDIM   256
#define GN     4
#define INP    32     // IN_POINTS
#define EIN    64     // EFF_IN
#define OUTP   128    // OUT_POINTS
#define EOUT   64     // EFF_OUT
#define TOTALP 8192   // per-group params (4096 M + 4096 S)
#define PCOLS  32768  // GN * TOTALP
#define SPLITK 8
#define KCHUNK 4096   // 32768 / SPLITK

// Scratch (device globals: allocation-free per harness rules)
__device__ float g_params[(size_t)NTOK * PCOLS];            // 471 MB
__device__ float g_z[(size_t)NTOK * PCOLS];                 // 471 MB
__device__ float g_part[(size_t)SPLITK * NTOK * QDIM];      // 29.5 MB

typedef unsigned long long ull;

__device__ __forceinline__ ull pack2(float lo, float hi) {
    ull r; asm("mov.b64 %0, {%1,%2};" : "=l"(r) : "f"(lo), "f"(hi)); return r;
}
__device__ __forceinline__ void unpack2(ull v, float& lo, float& hi) {
    asm("mov.b64 {%0,%1}, %2;" : "=f"(lo), "=f"(hi) : "l"(v));
}
// packed fp32 pair FMA: d = a*b + d (two FMAs per instruction on sm_103a)
__device__ __forceinline__ void fma2(ull& d, ull a, ull b) {
    asm("fma.rn.f32x2 %0, %1, %2, %0;" : "+l"(d) : "l"(a), "l"(b));
}

// ---------------------------------------------------------------------------
// Generic 128x128 SGEMM tile kernel, BK=8, double-buffered smem, f32x2 math.
// C[bz*M*ldc + row*ldc + col] (+= is NOT used; plain write) with optional bias.
// A row-major [M, lda_total], element k addressed as A[row*lda + bz*Kc + k]
// B row-major, Bb = B + bz*Kc*ldb + bx*128
// ---------------------------------------------------------------------------
__global__ __launch_bounds__(256, 2)
void sgemm128(const float* __restrict__ A, const float* __restrict__ B,
              float* __restrict__ C, int M, int N, int Kc,
              int lda, int ldb, int ldc, const float* __restrict__ bias)
{
    __shared__ float As[2][8 * 128];
    __shared__ float Bs[2][8 * 128];

    const int t  = threadIdx.x;
    const int bx = blockIdx.x, by = blockIdx.y, bz = blockIdx.z;

    const float* Ab = A + (size_t)bz * Kc;
    const float* Bb = B + (size_t)bz * Kc * ldb + (size_t)bx * 128;
    float*       Cb = C + (size_t)bz * M * ldc;

    const int row0g = by * 128;

    // global-load mapping
    const int ar = t >> 1;            // 0..127 (A row within tile)
    const int ac = (t & 1) * 4;       // 0 or 4 (k within BK)
    const int br = t >> 5;            // 0..7   (B k-row within BK)
    const int bc = (t & 31) * 4;      // 0..124 (B col within tile)

    // compute mapping: 8 warps as 4(row) x 2(col); lane as 4(row) x 8(col)
    const int w = t >> 5, lane = t & 31;
    const int wr = w & 3, wc = w >> 2;
    const int lr = lane >> 3, lc = lane & 7;
    const int trow = wr * 32 + lr * 8;   // 8 consecutive rows
    const int tcol = wc * 64 + lc * 8;   // 8 consecutive cols

    ull cc[8][4];
    #pragma unroll
    for (int i = 0; i < 8; i++)
        #pragma unroll
        for (int j = 0; j < 4; j++) cc[i][j] = 0ull;

    const int nk = Kc >> 3;

    float4 aReg, bReg;
    {   // prologue: tile 0
        int grow = row0g + ar;
        aReg = (grow < M) ? *(const float4*)(Ab + (size_t)grow * lda + ac)
                          : make_float4(0.f, 0.f, 0.f, 0.f);
        bReg = *(const float4*)(Bb + (size_t)br * ldb + bc);
        As[0][(ac + 0) * 128 + ar] = aReg.x;
        As[0][(ac + 1) * 128 + ar] = aReg.y;
        As[0][(ac + 2) * 128 + ar] = aReg.z;
        As[0][(ac + 3) * 128 + ar] = aReg.w;
        *(float4*)&Bs[0][br * 128 + bc] = bReg;
    }
    __syncthreads();

    for (int kt = 0; kt < nk; kt++) {
        const int cur = kt & 1;
        if (kt + 1 < nk) {
            const int kOff = (kt + 1) * 8;
            int grow = row0g + ar;
            aReg = (grow < M) ? *(const float4*)(Ab + (size_t)grow * lda + kOff + ac)
                              : make_float4(0.f, 0.f, 0.f, 0.f);
            bReg = *(const float4*)(Bb + (size_t)(kOff + br) * ldb + bc);
        }
        const float* Asc = As[cur];
        const float* Bsc = Bs[cur];
        #pragma unroll
        for (int k = 0; k < 8; k++) {
            float4 a0 = *(const float4*)&Asc[k * 128 + trow];
            float4 a1 = *(const float4*)&Asc[k * 128 + trow + 4];
            const ulonglong2* bp2 = (const ulonglong2*)&Bsc[k * 128 + tcol];
            ulonglong2 bb0 = bp2[0];
            ulonglong2 bb1 = bp2[1];
            ull b2[4] = {bb0.x, bb0.y, bb1.x, bb1.y};
            float av[8] = {a0.x, a0.y, a0.z, a0.w, a1.x, a1.y, a1.z, a1.w};
            #pragma unroll
            for (int i = 0; i < 8; i++) {
                ull ai = pack2(av[i], av[i]);
                fma2(cc[i][0], ai, b2[0]);
                fma2(cc[i][1], ai, b2[1]);
                fma2(cc[i][2], ai, b2[2]);
                fma2(cc[i][3], ai, b2[3]);
            }
        }
        if (kt + 1 < nk) {
            const int nxt = cur ^ 1;
            As[nxt][(ac + 0) * 128 + ar] = aReg.x;
            As[nxt][(ac + 1) * 128 + ar] = aReg.y;
            As[nxt][(ac + 2) * 128 + ar] = aReg.z;
            As[nxt][(ac + 3) * 128 + ar] = aReg.w;
            *(float4*)&Bs[nxt][br * 128 + bc] = bReg;
        }
        __syncthreads();
    }

    // epilogue
    const int gcol = bx * 128 + tcol;
    #pragma unroll
    for (int i = 0; i < 8; i++) {
        int grow = row0g + trow + i;
        if (grow >= M) continue;
        float v[8];
        unpack2(cc[i][0], v[0], v[1]);
        unpack2(cc[i][1], v[2], v[3]);
        unpack2(cc[i][2], v[4], v[5]);
        unpack2(cc[i][3], v[6], v[7]);
        if (bias) {
            #pragma unroll
            for (int j = 0; j < 8; j++) v[j] += bias[gcol + j];
        }
        float4* outp = (float4*)(Cb + (size_t)grow * ldc + gcol);
        outp[0] = make_float4(v[0], v[1], v[2], v[3]);
        outp[1] = make_float4(v[4], v[5], v[6], v[7]);
    }
}

// ---------------------------------------------------------------------------
// Block reduction of (sum, sumsq) over 256 threads / 8 warps.
// ---------------------------------------------------------------------------
__device__ __forceinline__ void blockReduce2(float& s, float& q, float* red)
{
    #pragma unroll
    for (int o = 16; o > 0; o >>= 1) {
        s += __shfl_xor_sync(0xffffffffu, s, o);
        q += __shfl_xor_sync(0xffffffffu, q, o);
    }
    const int t = threadIdx.x;
    if ((t & 31) == 0) { red[t >> 5] = s; red[8 + (t >> 5)] = q; }
    __syncthreads();
    s = 0.f; q = 0.f;
    #pragma unroll
    for (int i = 0; i < 8; i++) { s += red[i]; q += red[8 + i]; }
    __syncthreads();
}

// ---------------------------------------------------------------------------
// Fused middle: per (token, group):
//   out1 = relu(LN2d(x[32,64] @ M[64,64]))
//   out2 = relu(LN2d(S[128,32] @ out1[32,64]))  -> Z
// ---------------------------------------------------------------------------
__global__ __launch_bounds__(256)
void midkernel(const float* __restrict__ x, const float* __restrict__ params,
               float* __restrict__ Z)
{
    __shared__ float smem[12288];          // exactly 48 KB
    float* sX  = smem;                     // 2048: x tile [32][64]
    float* sM  = smem + 2048;              // 4096: M [64][64]
    float* sS  = smem + 6144;              // 4096: S [128][32]
    float* sO1 = smem + 10240;             // 2048: out1 normalized
    float* red = smem;                     // overlays sX (dead after stage 1)

    const int ng = blockIdx.x;             // n*4 + g
    const int t  = threadIdx.x;
    const float* xb = x + (size_t)ng * (INP * EIN);
    const float* pb = params + (size_t)(ng >> 2) * PCOLS + (size_t)(ng & 3) * TOTALP;

    {   // cooperative loads (vectorized)
        const float4* x4 = (const float4*)xb;
        const float4* m4 = (const float4*)pb;
        const float4* s4 = (const float4*)(pb + 4096);
        ((float4*)sX)[t]        = x4[t];
        ((float4*)sX)[t + 256]  = x4[t + 256];
        #pragma unroll
        for (int i = 0; i < 4; i++) {
            ((float4*)sM)[t + 256 * i] = m4[t + 256 * i];
            ((float4*)sS)[t + 256 * i] = s4[t + 256 * i];
        }
    }
    __syncthreads();

    // ---- stage 1: out1[p][o] = sum_c x[p][c] * M[c][o] ----
    const int p1 = t >> 3;          // 0..31
    const int og = (t & 7) << 3;    // 0,8,...,56
    ull acc1[4] = {0ull, 0ull, 0ull, 0ull};
    #pragma unroll 4
    for (int c = 0; c < 64; c++) {
        float xv = sX[p1 * 64 + c];
        ull xv2 = pack2(xv, xv);
        const ulonglong2* mp = (const ulonglong2*)(sM + c * 64 + og);
        ulonglong2 m0 = mp[0];
        ulonglong2 m1 = mp[1];
        fma2(acc1[0], xv2, m0.x);
        fma2(acc1[1], xv2, m0.y);
        fma2(acc1[2], xv2, m1.x);
        fma2(acc1[3], xv2, m1.y);
    }
    float v1[8];
    unpack2(acc1[0], v1[0], v1[1]);
    unpack2(acc1[1], v1[2], v1[3]);
    unpack2(acc1[2], v1[4], v1[5]);
    unpack2(acc1[3], v1[6], v1[7]);
    float s1 = 0.f, q1 = 0.f;
    #pragma unroll
    for (int j = 0; j < 8; j++) { s1 += v1[j]; q1 += v1[j] * v1[j]; }
    __syncthreads();                    // all sX reads done before red overlay
    blockReduce2(s1, q1, red);
    {
        float mean = s1 * (1.f / 2048.f);
        float var  = q1 * (1.f / 2048.f) - mean * mean;
        float rs   = rsqrtf(var + 1e-5f);
        #pragma unroll
        for (int j = 0; j < 8; j++)
            sO1[p1 * 64 + og + j] = fmaxf((v1[j] - mean) * rs, 0.f);
    }
    __syncthreads();

    // ---- stage 2: out2[q][o] = sum_p S[q][p] * out1n[p][o] ----
    const int ty = t >> 3;          // 0..31 -> q rows {ty, ty+32, ty+64, ty+96}
    const int tx = t & 7;           // cols tx*8 .. tx*8+7
    ull acc2[4][4];
    #pragma unroll
    for (int i = 0; i < 4; i++)
        #pragma unroll
        for (int j = 0; j < 4; j++) acc2[i][j] = 0ull;

    #pragma unroll 4
    for (int p = 0; p < 32; p++) {
        const ulonglong2* op = (const ulonglong2*)(sO1 + p * 64 + tx * 8);
        ulonglong2 b0 = op[0], b1 = op[1];
        #pragma unroll
        for (int i = 0; i < 4; i++) {
            float sv = sS[(ty + 32 * i) * 32 + p];
            ull sv2 = pack2(sv, sv);
            fma2(acc2[i][0], sv2, b0.x);
            fma2(acc2[i][1], sv2, b0.y);
            fma2(acc2[i][2], sv2, b1.x);
            fma2(acc2[i][3], sv2, b1.y);
        }
    }
    float v2[4][8];
    float s2 = 0.f, q2 = 0.f;
    #pragma unroll
    for (int i = 0; i < 4; i++) {
        unpack2(acc2[i][0], v2[i][0], v2[i][1]);
        unpack2(acc2[i][1], v2[i][2], v2[i][3]);
        unpack2(acc2[i][2], v2[i][4], v2[i][5]);
        unpack2(acc2[i][3], v2[i][6], v2[i][7]);
        #pragma unroll
        for (int j = 0; j < 8; j++) { s2 += v2[i][j]; q2 += v2[i][j] * v2[i][j]; }
    }
    blockReduce2(s2, q2, red);
    float mean2 = s2 * (1.f / 8192.f);
    float var2  = q2 * (1.f / 8192.f) - mean2 * mean2;
    float rs2   = rsqrtf(var2 + 1e-5f);

    float* zb = Z + (size_t)(ng >> 2) * PCOLS + (size_t)(ng & 3) * TOTALP;
    #pragma unroll
    for (int i = 0; i < 4; i++) {
        const int qrow = ty + 32 * i;
        float o[8];
        #pragma unroll
        for (int j = 0; j < 8; j++)
            o[j] = fmaxf((v2[i][j] - mean2) * rs2, 0.f);
        float4* zp = (float4*)(zb + qrow * 64 + tx * 8);
        zp[0] = make_float4(o[0], o[1], o[2], o[3]);
        zp[1] = make_float4(o[4], o[5], o[6], o[7]);
    }
}

// ---------------------------------------------------------------------------
// Final deterministic split-K reduce + bias + residual
// ---------------------------------------------------------------------------
__global__ void finalReduce(const float* __restrict__ part,
                            const float* __restrict__ query,
                            const float* __restrict__ bo,
                            float* __restrict__ out)
{
    int i = blockIdx.x * 256 + threadIdx.x;
    if (i >= NTOK * QDIM) return;
    float s = query[i] + bo[i & (QDIM - 1)];
    #pragma unroll
    for (int z = 0; z < SPLITK; z++)
        s += part[(size_t)z * NTOK * QDIM + i];
    out[i] = s;
}

// ---------------------------------------------------------------------------
extern "C" void kernel_launch(void* const* d_in, const int* in_sizes, int n_in,
                              void* d_out, int out_size)
{
    const float* x     = (const float*)d_in[0];
    const float* query = (const float*)d_in[1];
    const float* Wp    = (const float*)d_in[2];
    const float* bp    = (const float*)d_in[3];
    const float* Wo    = (const float*)d_in[4];
    const float* bo    = (const float*)d_in[5];
    float* out = (float*)d_out;

    float *pParams, *pZ, *pPart;
    cudaGetSymbolAddress((void**)&pParams, g_params);
    cudaGetSymbolAddress((void**)&pZ, g_z);
    cudaGetSymbolAddress((void**)&pPart, g_part);

    // GEMM1: params = query @ Wp + bp     [3600 x 32768], K=256
    sgemm128<<<dim3(PCOLS / 128, (NTOK + 127) / 128, 1), 256>>>(
        query, Wp, pParams, NTOK, PCOLS, 256, QDIM, PCOLS, PCOLS, bp);

    // fused middle: per (token, group)
    midkernel<<<NTOK * GN, 256>>>(x, pParams, pZ);

    // GEMM3 (split-K): part[z] = Z[:, z*4096:(z+1)*4096] @ Wo[z*4096:(z+1)*4096, :]
    sgemm128<<<dim3(QDIM / 128, (NTOK + 127) / 128, SPLITK), 256>>>(
        pZ, Wo, pPart, NTOK, QDIM, KCHUNK, PCOLS, QDIM, QDIM, nullptr);

    // out = query + sum_z part[z] + bo
    finalReduce<<<(NTOK * QDIM + 255) / 256, 256>>>(pPart, query, bo, out);
}

// round 3
// speedup vs baseline: 1.8883x; 1.8883x over previous
#include <cuda_runtime.h>
#include <cuda_bf16.h>
#include <cstdint>

// ---------------------------------------------------------------------------
// AdaptiveMixing on GB300 (compute_103 portable path):
//   params = query @ Wp + bp           [3600 x 32768]  (tensor: bf16-split mma.sync)
//   per (tok,grp): x@M -> LN -> relu -> S@ -> LN -> relu -> Z   (fp32 f32x2)
//   out = Z @ Wo + bo + query          [3600 x 256]    (tensor: bf16-split mma.sync)
// bf16 hi/lo split, 3 passes: C ~= Ah*Bh + Ah*Bl + Al*Bh  (rel err ~1e-5)
// ---------------------------------------------------------------------------
#define NTOK   3600
#define QDIM   256
#define PCOLS  32768
#define TOTALP 8192
#define INP    32
#define EIN    64
#define SPLITK 16

typedef unsigned long long ull;
typedef __nv_bfloat16 bf16;

// ------------------------- device scratch (no allocs) ----------------------
__device__ float g_params[(size_t)NTOK * PCOLS];
__device__ bf16  g_qhi[(size_t)NTOK * QDIM];
__device__ bf16  g_qlo[(size_t)NTOK * QDIM];
__device__ bf16  g_wpT_hi[(size_t)PCOLS * QDIM];
__device__ bf16  g_wpT_lo[(size_t)PCOLS * QDIM];
__device__ bf16  g_woT_hi[(size_t)QDIM * PCOLS];
__device__ bf16  g_woT_lo[(size_t)QDIM * PCOLS];
__device__ bf16  g_zhi[(size_t)NTOK * PCOLS];
__device__ bf16  g_zlo[(size_t)NTOK * PCOLS];
__device__ float g_part[(size_t)SPLITK * NTOK * QDIM];

// ----------------------------- helpers -------------------------------------
__device__ __forceinline__ ull pack2(float lo, float hi) {
    ull r; asm("mov.b64 %0, {%1,%2};" : "=l"(r) : "f"(lo), "f"(hi)); return r;
}
__device__ __forceinline__ void unpack2(ull v, float& lo, float& hi) {
    asm("mov.b64 {%0,%1}, %2;" : "=f"(lo), "=f"(hi) : "l"(v));
}
__device__ __forceinline__ void fma2(ull& d, ull a, ull b) {
    asm("fma.rn.f32x2 %0, %1, %2, %0;" : "+l"(d) : "l"(a), "l"(b));
}
__device__ __forceinline__ void f2hilo(float v, bf16& h, bf16& l) {
    h = __float2bfloat16(v);
    l = __float2bfloat16(v - __bfloat162float(h));
}
__device__ __forceinline__ unsigned bpk(bf16 a, bf16 b) {
    return (unsigned)__bfloat16_as_ushort(a) | ((unsigned)__bfloat16_as_ushort(b) << 16);
}
__device__ __forceinline__ uint32_t smem_u32(const void* p) {
    uint32_t a;
    asm("{ .reg .u64 t; cvta.to.shared.u64 t, %1; cvt.u32.u64 %0, t; }" : "=r"(a) : "l"(p));
    return a;
}
__device__ __forceinline__ void ldsm4(uint32_t& r0, uint32_t& r1, uint32_t& r2, uint32_t& r3,
                                      uint32_t addr) {
    asm volatile("ldmatrix.sync.aligned.m8n8.x4.shared.b16 {%0,%1,%2,%3}, [%4];"
                 : "=r"(r0), "=r"(r1), "=r"(r2), "=r"(r3) : "r"(addr));
}
__device__ __forceinline__ void mma_bf16(float* c, const uint32_t* a, const uint32_t* b) {
    asm volatile(
        "mma.sync.aligned.m16n8k16.row.col.f32.bf16.bf16.f32 "
        "{%0,%1,%2,%3}, {%4,%5,%6,%7}, {%8,%9}, {%0,%1,%2,%3};"
        : "+f"(c[0]), "+f"(c[1]), "+f"(c[2]), "+f"(c[3])
        : "r"(a[0]), "r"(a[1]), "r"(a[2]), "r"(a[3]), "r"(b[0]), "r"(b[1]));
}

// ---------------------------------------------------------------------------
// Conversion kernels
// ---------------------------------------------------------------------------
__global__ void convQ(const float* __restrict__ q, bf16* __restrict__ hi, bf16* __restrict__ lo) {
    int i = blockIdx.x * 256 + threadIdx.x;
    if (i >= NTOK * QDIM / 4) return;
    float4 v = ((const float4*)q)[i];
    bf16 h0,l0,h1,l1,h2,l2,h3,l3;
    f2hilo(v.x,h0,l0); f2hilo(v.y,h1,l1); f2hilo(v.z,h2,l2); f2hilo(v.w,h3,l3);
    ((uint2*)hi)[i] = make_uint2(bpk(h0,h1), bpk(h2,h3));
    ((uint2*)lo)[i] = make_uint2(bpk(l0,l1), bpk(l2,l3));
}

// transpose + split: in [R][C] f32 -> out[C][R] bf16 hi/lo
__global__ void transConv(const float* __restrict__ in, bf16* __restrict__ oHi,
                          bf16* __restrict__ oLo, int R, int C) {
    __shared__ float tile[32][33];
    int c0 = blockIdx.x * 32, r0 = blockIdx.y * 32;
    int tx = threadIdx.x, ty = threadIdx.y;    // 32 x 8
    #pragma unroll
    for (int i = 0; i < 4; i++)
        tile[ty + 8 * i][tx] = in[(size_t)(r0 + ty + 8 * i) * C + c0 + tx];
    __syncthreads();
    #pragma unroll
    for (int i = 0; i < 4; i++) {
        float v = tile[tx][ty + 8 * i];
        bf16 h, l; f2hilo(v, h, l);
        size_t o = (size_t)(c0 + ty + 8 * i) * R + r0 + tx;
        oHi[o] = h; oLo[o] = l;
    }
}

// ---------------------------------------------------------------------------
// bf16-split GEMM via mma.sync:  C[128m x 128n] tiles, BK=32, 8 warps (4x2),
// warp tile 32x64.  B pre-transposed: B[n][k].  3 passes per k-chunk.
// smem row pitch 40 bf16 (80 B) -> conflict-free ldmatrix.
// ---------------------------------------------------------------------------
#define TILE_B   10240                   // 128 rows * 40 bf16 * 2
#define STAGE_B  (4 * TILE_B)            // Ah, Al, Bh, Bl
#define GSMEM    (2 * STAGE_B)           // 81920 bytes

__global__ __launch_bounds__(256)
void gemm_mma(const bf16* __restrict__ Ahi, const bf16* __restrict__ Alo,
              const bf16* __restrict__ Bhi, const bf16* __restrict__ Blo,
              float* __restrict__ C, const float* __restrict__ bias,
              int M, int lda, int ldb, int ldc, int nChunks, int partStride)
{
    extern __shared__ char smem[];
    const uint32_t sm0 = smem_u32(smem);
    const int t = threadIdx.x, lane = t & 31, w = t >> 5;
    const int wr = w & 3, wc = w >> 2;
    const int mrow0 = blockIdx.y * 128;
    const int n0 = blockIdx.x * 128;
    const int k0 = blockIdx.z * nChunks * 32;
    float* Cb = C + (size_t)blockIdx.z * partStride;

    // global <-> smem staging mapping (2 uint4 per thread per buffer)
    const int row0_ = t >> 2, seg0 = t & 3;                 // idx = t
    const int row1_ = (t + 256) >> 2, seg1 = (t + 256) & 3; // idx = t+256
    const uint32_t so0 = (uint32_t)(row0_ * 40 + seg0 * 8) * 2;
    const uint32_t so1 = (uint32_t)(row1_ * 40 + seg1 * 8) * 2;
    const uint4 zz = make_uint4(0, 0, 0, 0);

    // ldmatrix fragment offsets
    const int q = lane >> 3, r8 = lane & 7;
    const uint32_t aoff = (uint32_t)((wr * 32 + r8 + ((q & 1) << 3)) * 40 + ((q >> 1) << 3)) * 2;
    const uint32_t boff = (uint32_t)((wc * 64 + r8 + ((q >> 1) << 3)) * 40 + ((q & 1) << 3)) * 2;

    float c[2][8][4];
    #pragma unroll
    for (int mt = 0; mt < 2; mt++)
        #pragma unroll
        for (int nt = 0; nt < 8; nt++)
            #pragma unroll
            for (int j = 0; j < 4; j++) c[mt][nt][j] = 0.f;

    uint4 pf[8];
    // prologue load chunk 0
    {
        const int kk = k0;
        bool ok0 = (mrow0 + row0_) < M, ok1 = (mrow0 + row1_) < M;
        size_t ga0 = (size_t)(mrow0 + row0_) * lda + kk + seg0 * 8;
        size_t ga1 = (size_t)(mrow0 + row1_) * lda + kk + seg1 * 8;
        size_t gb0 = (size_t)(n0 + row0_) * ldb + kk + seg0 * 8;
        size_t gb1 = (size_t)(n0 + row1_) * ldb + kk + seg1 * 8;
        pf[0] = ok0 ? *(const uint4*)(Ahi + ga0) : zz;
        pf[1] = ok0 ? *(const uint4*)(Alo + ga0) : zz;
        pf[2] = *(const uint4*)(Bhi + gb0);
        pf[3] = *(const uint4*)(Blo + gb0);
        pf[4] = ok1 ? *(const uint4*)(Ahi + ga1) : zz;
        pf[5] = ok1 ? *(const uint4*)(Alo + ga1) : zz;
        pf[6] = *(const uint4*)(Bhi + gb1);
        pf[7] = *(const uint4*)(Blo + gb1);
        char* st = smem;
        *(uint4*)(st + 0 * TILE_B + so0) = pf[0];
        *(uint4*)(st + 1 * TILE_B + so0) = pf[1];
        *(uint4*)(st + 2 * TILE_B + so0) = pf[2];
        *(uint4*)(st + 3 * TILE_B + so0) = pf[3];
        *(uint4*)(st + 0 * TILE_B + so1) = pf[4];
        *(uint4*)(st + 1 * TILE_B + so1) = pf[5];
        *(uint4*)(st + 2 * TILE_B + so1) = pf[6];
        *(uint4*)(st + 3 * TILE_B + so1) = pf[7];
    }
    __syncthreads();

    for (int ch = 0; ch < nChunks; ch++) {
        const int st = ch & 1;
        const bool more = (ch + 1) < nChunks;
        if (more) {
            const int kk = k0 + (ch + 1) * 32;
            bool ok0 = (mrow0 + row0_) < M, ok1 = (mrow0 + row1_) < M;
            size_t ga0 = (size_t)(mrow0 + row0_) * lda + kk + seg0 * 8;
            size_t ga1 = (size_t)(mrow0 + row1_) * lda + kk + seg1 * 8;
            size_t gb0 = (size_t)(n0 + row0_) * ldb + kk + seg0 * 8;
            size_t gb1 = (size_t)(n0 + row1_) * ldb + kk + seg1 * 8;
            pf[0] = ok0 ? *(const uint4*)(Ahi + ga0) : zz;
            pf[1] = ok0 ? *(const uint4*)(Alo + ga0) : zz;
            pf[2] = *(const uint4*)(Bhi + gb0);
            pf[3] = *(const uint4*)(Blo + gb0);
            pf[4] = ok1 ? *(const uint4*)(Ahi + ga1) : zz;
            pf[5] = ok1 ? *(const uint4*)(Alo + ga1) : zz;
            pf[6] = *(const uint4*)(Bhi + gb1);
            pf[7] = *(const uint4*)(Blo + gb1);
        }

        // compute on stage st
        const uint32_t base = sm0 + st * STAGE_B;
        #pragma unroll
        for (int ks = 0; ks < 2; ks++) {
            uint32_t ah[2][4], al2[2][4];
            #pragma unroll
            for (int mt = 0; mt < 2; mt++) {
                uint32_t aA = base + aoff + mt * (16 * 80) + ks * 32;
                ldsm4(ah[mt][0], ah[mt][1], ah[mt][2], ah[mt][3], aA);
                ldsm4(al2[mt][0], al2[mt][1], al2[mt][2], al2[mt][3], aA + TILE_B);
            }
            uint32_t bh[4][4], bl[4][4];
            #pragma unroll
            for (int g = 0; g < 4; g++) {
                uint32_t aB = base + 2 * TILE_B + boff + g * (16 * 80) + ks * 32;
                ldsm4(bh[g][0], bh[g][1], bh[g][2], bh[g][3], aB);
                ldsm4(bl[g][0], bl[g][1], bl[g][2], bl[g][3], aB + TILE_B);
            }
            #pragma unroll
            for (int mt = 0; mt < 2; mt++)
                #pragma unroll
                for (int g = 0; g < 4; g++) {
                    mma_bf16(c[mt][2*g],   ah[mt],  &bh[g][0]);
                    mma_bf16(c[mt][2*g+1], ah[mt],  &bh[g][2]);
                    mma_bf16(c[mt][2*g],   ah[mt],  &bl[g][0]);
                    mma_bf16(c[mt][2*g+1], ah[mt],  &bl[g][2]);
                    mma_bf16(c[mt][2*g],   al2[mt], &bh[g][0]);
                    mma_bf16(c[mt][2*g+1], al2[mt], &bh[g][2]);
                }
        }

        if (more) {
            char* sd = smem + (st ^ 1) * STAGE_B;
            *(uint4*)(sd + 0 * TILE_B + so0) = pf[0];
            *(uint4*)(sd + 1 * TILE_B + so0) = pf[1];
            *(uint4*)(sd + 2 * TILE_B + so0) = pf[2];
            *(uint4*)(sd + 3 * TILE_B + so0) = pf[3];
            *(uint4*)(sd + 0 * TILE_B + so1) = pf[4];
            *(uint4*)(sd + 1 * TILE_B + so1) = pf[5];
            *(uint4*)(sd + 2 * TILE_B + so1) = pf[6];
            *(uint4*)(sd + 3 * TILE_B + so1) = pf[7];
        }
        __syncthreads();
    }

    // epilogue
    const int crow = mrow0 + wr * 32 + (lane >> 2);
    const int ccol = n0 + wc * 64 + (lane & 3) * 2;
    #pragma unroll
    for (int mt = 0; mt < 2; mt++) {
        #pragma unroll
        for (int nt = 0; nt < 8; nt++) {
            int col = ccol + nt * 8;
            float b0 = 0.f, b1 = 0.f;
            if (bias) { b0 = bias[col]; b1 = bias[col + 1]; }
            int r0 = crow + mt * 16;
            if (r0 < M) {
                float2 v = make_float2(c[mt][nt][0] + b0, c[mt][nt][1] + b1);
                *(float2*)(Cb + (size_t)r0 * ldc + col) = v;
            }
            int r1 = r0 + 8;
            if (r1 < M) {
                float2 v = make_float2(c[mt][nt][2] + b0, c[mt][nt][3] + b1);
                *(float2*)(Cb + (size_t)r1 * ldc + col) = v;
            }
        }
    }
}

// ---------------------------------------------------------------------------
// Block reduction (sum, sumsq) over 256 threads
// ---------------------------------------------------------------------------
__device__ __forceinline__ void blockReduce2(float& s, float& q, float* red) {
    #pragma unroll
    for (int o = 16; o > 0; o >>= 1) {
        s += __shfl_xor_sync(0xffffffffu, s, o);
        q += __shfl_xor_sync(0xffffffffu, q, o);
    }
    const int t = threadIdx.x;
    if ((t & 31) == 0) { red[t >> 5] = s; red[8 + (t >> 5)] = q; }
    __syncthreads();
    s = 0.f; q = 0.f;
    #pragma unroll
    for (int i = 0; i < 8; i++) { s += red[i]; q += red[8 + i]; }
    __syncthreads();
}

// ---------------------------------------------------------------------------
// Fused middle: per (token, group); outputs Z as bf16 hi/lo
// ---------------------------------------------------------------------------
__global__ __launch_bounds__(256)
void midkernel(const float* __restrict__ x, const float* __restrict__ params,
               bf16* __restrict__ Zhi, bf16* __restrict__ Zlo)
{
    __shared__ float smem[12288];
    float* sX  = smem;
    float* sM  = smem + 2048;
    float* sS  = smem + 6144;
    float* sO1 = smem + 10240;
    float* red = smem;

    const int ng = blockIdx.x;
    const int t  = threadIdx.x;
    const float* xb = x + (size_t)ng * (INP * EIN);
    const float* pb = params + (size_t)(ng >> 2) * PCOLS + (size_t)(ng & 3) * TOTALP;

    {
        const float4* x4 = (const float4*)xb;
        const float4* m4 = (const float4*)pb;
        const float4* s4 = (const float4*)(pb + 4096);
        ((float4*)sX)[t]       = x4[t];
        ((float4*)sX)[t + 256] = x4[t + 256];
        #pragma unroll
        for (int i = 0; i < 4; i++) {
            ((float4*)sM)[t + 256 * i] = m4[t + 256 * i];
            ((float4*)sS)[t + 256 * i] = s4[t + 256 * i];
        }
    }
    __syncthreads();

    // stage 1: out1 = x[32,64] @ M[64,64]
    const int p1 = t >> 3;
    const int og = (t & 7) << 3;
    ull acc1[4] = {0ull, 0ull, 0ull, 0ull};
    #pragma unroll 4
    for (int cix = 0; cix < 64; cix++) {
        float xv = sX[p1 * 64 + cix];
        ull xv2 = pack2(xv, xv);
        const ulonglong2* mp = (const ulonglong2*)(sM + cix * 64 + og);
        ulonglong2 m0 = mp[0], m1 = mp[1];
        fma2(acc1[0], xv2, m0.x); fma2(acc1[1], xv2, m0.y);
        fma2(acc1[2], xv2, m1.x); fma2(acc1[3], xv2, m1.y);
    }
    float v1[8];
    unpack2(acc1[0], v1[0], v1[1]); unpack2(acc1[1], v1[2], v1[3]);
    unpack2(acc1[2], v1[4], v1[5]); unpack2(acc1[3], v1[6], v1[7]);
    float s1 = 0.f, q1 = 0.f;
    #pragma unroll
    for (int j = 0; j < 8; j++) { s1 += v1[j]; q1 += v1[j] * v1[j]; }
    __syncthreads();
    blockReduce2(s1, q1, red);
    {
        float mean = s1 * (1.f / 2048.f);
        float var  = q1 * (1.f / 2048.f) - mean * mean;
        float rs   = rsqrtf(var + 1e-5f);
        #pragma unroll
        for (int j = 0; j < 8; j++)
            sO1[p1 * 64 + og + j] = fmaxf((v1[j] - mean) * rs, 0.f);
    }
    __syncthreads();

    // stage 2: out2 = S[128,32] @ out1n[32,64]
    const int ty = t >> 3;
    const int tx = t & 7;
    ull acc2[4][4];
    #pragma unroll
    for (int i = 0; i < 4; i++)
        #pragma unroll
        for (int j = 0; j < 4; j++) acc2[i][j] = 0ull;

    #pragma unroll 4
    for (int p = 0; p < 32; p++) {
        const ulonglong2* op = (const ulonglong2*)(sO1 + p * 64 + tx * 8);
        ulonglong2 b0 = op[0], b1 = op[1];
        #pragma unroll
        for (int i = 0; i < 4; i++) {
            float sv = sS[(ty + 32 * i) * 32 + p];
            ull sv2 = pack2(sv, sv);
            fma2(acc2[i][0], sv2, b0.x); fma2(acc2[i][1], sv2, b0.y);
            fma2(acc2[i][2], sv2, b1.x); fma2(acc2[i][3], sv2, b1.y);
        }
    }
    float v2[4][8];
    float s2 = 0.f, q2 = 0.f;
    #pragma unroll
    for (int i = 0; i < 4; i++) {
        unpack2(acc2[i][0], v2[i][0], v2[i][1]); unpack2(acc2[i][1], v2[i][2], v2[i][3]);
        unpack2(acc2[i][2], v2[i][4], v2[i][5]); unpack2(acc2[i][3], v2[i][6], v2[i][7]);
        #pragma unroll
        for (int j = 0; j < 8; j++) { s2 += v2[i][j]; q2 += v2[i][j] * v2[i][j]; }
    }
    blockReduce2(s2, q2, red);
    float mean2 = s2 * (1.f / 8192.f);
    float var2  = q2 * (1.f / 8192.f) - mean2 * mean2;
    float rs2   = rsqrtf(var2 + 1e-5f);

    const size_t zbase = (size_t)(ng >> 2) * PCOLS + (size_t)(ng & 3) * TOTALP;
    #pragma unroll
    for (int i = 0; i < 4; i++) {
        const int qrow = ty + 32 * i;
        bf16 h[8], l[8];
        #pragma unroll
        for (int j = 0; j < 8; j++) {
            float o = fmaxf((v2[i][j] - mean2) * rs2, 0.f);
            f2hilo(o, h[j], l[j]);
        }
        size_t off = zbase + (size_t)qrow * 64 + tx * 8;
        *(uint4*)(Zhi + off) = make_uint4(bpk(h[0],h[1]), bpk(h[2],h[3]), bpk(h[4],h[5]), bpk(h[6],h[7]));
        *(uint4*)(Zlo + off) = make_uint4(bpk(l[0],l[1]), bpk(l[2],l[3]), bpk(l[4],l[5]), bpk(l[6],l[7]));
    }
}

// ---------------------------------------------------------------------------
__global__ void finalReduce(const float* __restrict__ part,
                            const float* __restrict__ query,
                            const float* __restrict__ bo,
                            float* __restrict__ out)
{
    int i = blockIdx.x * 256 + threadIdx.x;
    if (i >= NTOK * QDIM) return;
    float s = query[i] + bo[i & (QDIM - 1)];
    #pragma unroll
    for (int z = 0; z < SPLITK; z++)
        s += part[(size_t)z * NTOK * QDIM + i];
    out[i] = s;
}

// ---------------------------------------------------------------------------
extern "C" void kernel_launch(void* const* d_in, const int* in_sizes, int n_in,
                              void* d_out, int out_size)
{
    const float* x     = (const float*)d_in[0];
    const float* query = (const float*)d_in[1];
    const float* Wp    = (const float*)d_in[2];
    const float* bp    = (const float*)d_in[3];
    const float* Wo    = (const float*)d_in[4];
    const float* bo    = (const float*)d_in[5];
    float* out = (float*)d_out;

    float *pParams, *pPart;
    bf16 *pQh, *pQl, *pWpTh, *pWpTl, *pWoTh, *pWoTl, *pZh, *pZl;
    cudaGetSymbolAddress((void**)&pParams, g_params);
    cudaGetSymbolAddress((void**)&pPart, g_part);
    cudaGetSymbolAddress((void**)&pQh, g_qhi);
    cudaGetSymbolAddress((void**)&pQl, g_qlo);
    cudaGetSymbolAddress((void**)&pWpTh, g_wpT_hi);
    cudaGetSymbolAddress((void**)&pWpTl, g_wpT_lo);
    cudaGetSymbolAddress((void**)&pWoTh, g_woT_hi);
    cudaGetSymbolAddress((void**)&pWoTl, g_woT_lo);
    cudaGetSymbolAddress((void**)&pZh, g_zhi);
    cudaGetSymbolAddress((void**)&pZl, g_zlo);

    cudaFuncSetAttribute(gemm_mma, cudaFuncAttributeMaxDynamicSharedMemorySize, GSMEM);

    // conversions
    convQ<<<(NTOK * QDIM / 4 + 255) / 256, 256>>>(query, pQh, pQl);
    transConv<<<dim3(PCOLS / 32, QDIM / 32), dim3(32, 8)>>>(Wp, pWpTh, pWpTl, QDIM, PCOLS);
    transConv<<<dim3(QDIM / 32, PCOLS / 32), dim3(32, 8)>>>(Wo, pWoTh, pWoTl, PCOLS, QDIM);

    // GEMM1: params[3600,32768] = q @ Wp + bp   (K=256 -> 8 chunks of 32)
    gemm_mma<<<dim3(PCOLS / 128, 29, 1), 256, GSMEM>>>(
        pQh, pQl, pWpTh, pWpTl, pParams, bp,
        NTOK, QDIM, QDIM, PCOLS, 8, 0);

    // fused middle -> Z (bf16 hi/lo)
    midkernel<<<NTOK * 4, 256>>>(x, pParams, pZh, pZl);

    // GEMM3: part[z][3600,256] = Z[:, z*2048 : (z+1)*2048] @ Wo-chunk
    gemm_mma<<<dim3(QDIM / 128, 29, SPLITK), 256, GSMEM>>>(
        pZh, pZl, pWoTh, pWoTl, pPart, nullptr,
        NTOK, PCOLS, PCOLS, QDIM, (PCOLS / SPLITK) / 32, (int)((size_t)NTOK * QDIM));

    finalReduce<<<(NTOK * QDIM + 255) / 256, 256>>>(pPart, query, bo, out);
}

// round 4
// speedup vs baseline: 2.1078x; 1.1163x over previous
#include <cuda_runtime.h>
#include <cuda_bf16.h>
#include <cstdint>

// ---------------------------------------------------------------------------
// AdaptiveMixing on GB300 (compute_103 portable path):
//   params = query @ Wp + bp           [3600 x 32768]  (bf16-split mma.sync)
//   per (tok,grp): x@M -> LN -> relu -> S@ -> LN -> relu -> Z   (fp32 f32x2)
//   out = Z @ Wo + bo + query          [3600 x 256]    (bf16-split mma.sync)
// bf16 hi/lo split, 3 passes: C ~= Ah*Bh + Ah*Bl + Al*Bh  (rel err ~1e-5)
// R4: cp.async staging + __launch_bounds__(256,2) to get 2 CTAs/SM.
// ---------------------------------------------------------------------------
#define NTOK   3600
#define QDIM   256
#define PCOLS  32768
#define TOTALP 8192
#define INP    32
#define EIN    64
#define SPLITK 16

typedef unsigned long long ull;
typedef __nv_bfloat16 bf16;

// ------------------------- device scratch (no allocs) ----------------------
__device__ float g_params[(size_t)NTOK * PCOLS];
__device__ bf16  g_qhi[(size_t)NTOK * QDIM];
__device__ bf16  g_qlo[(size_t)NTOK * QDIM];
__device__ bf16  g_wpT_hi[(size_t)PCOLS * QDIM];
__device__ bf16  g_wpT_lo[(size_t)PCOLS * QDIM];
__device__ bf16  g_woT_hi[(size_t)QDIM * PCOLS];
__device__ bf16  g_woT_lo[(size_t)QDIM * PCOLS];
__device__ bf16  g_zhi[(size_t)NTOK * PCOLS];
__device__ bf16  g_zlo[(size_t)NTOK * PCOLS];
__device__ float g_part[(size_t)SPLITK * NTOK * QDIM];

// ----------------------------- helpers -------------------------------------
__device__ __forceinline__ ull pack2(float lo, float hi) {
    ull r; asm("mov.b64 %0, {%1,%2};" : "=l"(r) : "f"(lo), "f"(hi)); return r;
}
__device__ __forceinline__ void unpack2(ull v, float& lo, float& hi) {
    asm("mov.b64 {%0,%1}, %2;" : "=f"(lo), "=f"(hi) : "l"(v));
}
__device__ __forceinline__ void fma2(ull& d, ull a, ull b) {
    asm("fma.rn.f32x2 %0, %1, %2, %0;" : "+l"(d) : "l"(a), "l"(b));
}
__device__ __forceinline__ void f2hilo(float v, bf16& h, bf16& l) {
    h = __float2bfloat16(v);
    l = __float2bfloat16(v - __bfloat162float(h));
}
__device__ __forceinline__ unsigned bpk(bf16 a, bf16 b) {
    return (unsigned)__bfloat16_as_ushort(a) | ((unsigned)__bfloat16_as_ushort(b) << 16);
}
__device__ __forceinline__ uint32_t smem_u32(const void* p) {
    uint32_t a;
    asm("{ .reg .u64 t; cvta.to.shared.u64 t, %1; cvt.u32.u64 %0, t; }" : "=r"(a) : "l"(p));
    return a;
}
__device__ __forceinline__ void ldsm4(uint32_t& r0, uint32_t& r1, uint32_t& r2, uint32_t& r3,
                                      uint32_t addr) {
    asm volatile("ldmatrix.sync.aligned.m8n8.x4.shared.b16 {%0,%1,%2,%3}, [%4];"
                 : "=r"(r0), "=r"(r1), "=r"(r2), "=r"(r3) : "r"(addr));
}
__device__ __forceinline__ void mma_bf16(float* c, const uint32_t* a, const uint32_t* b) {
    asm volatile(
        "mma.sync.aligned.m16n8k16.row.col.f32.bf16.bf16.f32 "
        "{%0,%1,%2,%3}, {%4,%5,%6,%7}, {%8,%9}, {%0,%1,%2,%3};"
        : "+f"(c[0]), "+f"(c[1]), "+f"(c[2]), "+f"(c[3])
        : "r"(a[0]), "r"(a[1]), "r"(a[2]), "r"(a[3]), "r"(b[0]), "r"(b[1]));
}
__device__ __forceinline__ void cpa16(uint32_t dst, const void* src, int sz) {
    asm volatile("cp.async.cg.shared.global [%0], [%1], 16, %2;"
                 :: "r"(dst), "l"(src), "r"(sz) : "memory");
}
#define CP_COMMIT() asm volatile("cp.async.commit_group;" ::: "memory")
#define CP_WAIT(n)  asm volatile("cp.async.wait_group %0;" :: "n"(n) : "memory")

// ---------------------------------------------------------------------------
// Conversion kernels
// ---------------------------------------------------------------------------
__global__ void convQ(const float* __restrict__ q, bf16* __restrict__ hi, bf16* __restrict__ lo) {
    int i = blockIdx.x * 256 + threadIdx.x;
    if (i >= NTOK * QDIM / 4) return;
    float4 v = ((const float4*)q)[i];
    bf16 h0,l0,h1,l1,h2,l2,h3,l3;
    f2hilo(v.x,h0,l0); f2hilo(v.y,h1,l1); f2hilo(v.z,h2,l2); f2hilo(v.w,h3,l3);
    ((uint2*)hi)[i] = make_uint2(bpk(h0,h1), bpk(h2,h3));
    ((uint2*)lo)[i] = make_uint2(bpk(l0,l1), bpk(l2,l3));
}

// transpose + split: in [R][C] f32 -> out[C][R] bf16 hi/lo
__global__ void transConv(const float* __restrict__ in, bf16* __restrict__ oHi,
                          bf16* __restrict__ oLo, int R, int C) {
    __shared__ float tile[32][33];
    int c0 = blockIdx.x * 32, r0 = blockIdx.y * 32;
    int tx = threadIdx.x, ty = threadIdx.y;    // 32 x 8
    #pragma unroll
    for (int i = 0; i < 4; i++)
        tile[ty + 8 * i][tx] = in[(size_t)(r0 + ty + 8 * i) * C + c0 + tx];
    __syncthreads();
    #pragma unroll
    for (int i = 0; i < 4; i++) {
        float v = tile[tx][ty + 8 * i];
        bf16 h, l; f2hilo(v, h, l);
        size_t o = (size_t)(c0 + ty + 8 * i) * R + r0 + tx;
        oHi[o] = h; oLo[o] = l;
    }
}

// ---------------------------------------------------------------------------
// bf16-split GEMM via mma.sync:  C[128m x 128n] tiles, BK=32, 8 warps (4x2),
// warp tile 32x64.  B pre-transposed: B[n][k].  3 passes per k-chunk.
// smem row pitch 40 bf16 (80 B) -> conflict-free ldmatrix.
// cp.async double-buffer; 2 CTAs/SM.
// ---------------------------------------------------------------------------
#define TILE_B   10240                   // 128 rows * 40 bf16 * 2
#define STAGE_B  (4 * TILE_B)            // Ah, Al, Bh, Bl
#define GSMEM    (2 * STAGE_B)           // 81920 bytes

__global__ __launch_bounds__(256, 2)
void gemm_mma(const bf16* __restrict__ Ahi, const bf16* __restrict__ Alo,
              const bf16* __restrict__ Bhi, const bf16* __restrict__ Blo,
              float* __restrict__ C, const float* __restrict__ bias,
              int M, int lda, int ldb, int ldc, int nChunks, int partStride)
{
    extern __shared__ char smem[];
    const uint32_t sm0 = smem_u32(smem);
    const int t = threadIdx.x, lane = t & 31, w = t >> 5;
    const int wr = w & 3, wc = w >> 2;
    const int mrow0 = blockIdx.y * 128;
    const int n0 = blockIdx.x * 128;
    const int k0 = blockIdx.z * nChunks * 32;
    float* Cb = C + (size_t)blockIdx.z * partStride;

    // staging mapping: each thread covers 2 (row, 8-elem seg) slots per tile
    const int row0_ = t >> 2, seg0 = t & 3;
    const int row1_ = (t + 256) >> 2, seg1 = (t + 256) & 3;
    const uint32_t so0 = (uint32_t)(row0_ * 40 + seg0 * 8) * 2;
    const uint32_t so1 = (uint32_t)(row1_ * 40 + seg1 * 8) * 2;
    const int okA0 = ((mrow0 + row0_) < M) ? 16 : 0;
    const int okA1 = ((mrow0 + row1_) < M) ? 16 : 0;
    const size_t gaBase0 = (size_t)(mrow0 + row0_) * lda + seg0 * 8;
    const size_t gaBase1 = (size_t)(mrow0 + row1_) * lda + seg1 * 8;
    const size_t gbBase0 = (size_t)(n0 + row0_) * ldb + seg0 * 8;
    const size_t gbBase1 = (size_t)(n0 + row1_) * ldb + seg1 * 8;

    // ldmatrix fragment offsets
    const int q = lane >> 3, r8 = lane & 7;
    const uint32_t aoff = (uint32_t)((wr * 32 + r8 + ((q & 1) << 3)) * 40 + ((q >> 1) << 3)) * 2;
    const uint32_t boff = (uint32_t)((wc * 64 + r8 + ((q >> 1) << 3)) * 40 + ((q & 1) << 3)) * 2;

    float c[2][8][4];
    #pragma unroll
    for (int mt = 0; mt < 2; mt++)
        #pragma unroll
        for (int nt = 0; nt < 8; nt++)
            #pragma unroll
            for (int j = 0; j < 4; j++) c[mt][nt][j] = 0.f;

    // cp.async one stage (8 x 16B per thread)
    auto stageLoad = [&](int stage, int kk) {
        uint32_t sb = sm0 + stage * STAGE_B;
        cpa16(sb + 0 * TILE_B + so0, Ahi + gaBase0 + kk, okA0);
        cpa16(sb + 1 * TILE_B + so0, Alo + gaBase0 + kk, okA0);
        cpa16(sb + 2 * TILE_B + so0, Bhi + gbBase0 + kk, 16);
        cpa16(sb + 3 * TILE_B + so0, Blo + gbBase0 + kk, 16);
        cpa16(sb + 0 * TILE_B + so1, Ahi + gaBase1 + kk, okA1);
        cpa16(sb + 1 * TILE_B + so1, Alo + gaBase1 + kk, okA1);
        cpa16(sb + 2 * TILE_B + so1, Bhi + gbBase1 + kk, 16);
        cpa16(sb + 3 * TILE_B + so1, Blo + gbBase1 + kk, 16);
        CP_COMMIT();
    };

    stageLoad(0, k0);

    for (int ch = 0; ch < nChunks; ch++) {
        const int st = ch & 1;
        const bool more = (ch + 1) < nChunks;
        if (more) stageLoad(st ^ 1, k0 + (ch + 1) * 32);
        if (more) { CP_WAIT(1); } else { CP_WAIT(0); }
        __syncthreads();

        const uint32_t base = sm0 + st * STAGE_B;
        #pragma unroll
        for (int ks = 0; ks < 2; ks++) {
            uint32_t ah[2][4], al2[2][4];
            #pragma unroll
            for (int mt = 0; mt < 2; mt++) {
                uint32_t aA = base + aoff + mt * (16 * 80) + ks * 32;
                ldsm4(ah[mt][0], ah[mt][1], ah[mt][2], ah[mt][3], aA);
                ldsm4(al2[mt][0], al2[mt][1], al2[mt][2], al2[mt][3], aA + TILE_B);
            }
            #pragma unroll
            for (int g = 0; g < 4; g++) {
                uint32_t bh[4], bl[4];
                uint32_t aB = base + 2 * TILE_B + boff + g * (16 * 80) + ks * 32;
                ldsm4(bh[0], bh[1], bh[2], bh[3], aB);
                ldsm4(bl[0], bl[1], bl[2], bl[3], aB + TILE_B);
                #pragma unroll
                for (int mt = 0; mt < 2; mt++) {
                    mma_bf16(c[mt][2*g],   ah[mt],  &bh[0]);
                    mma_bf16(c[mt][2*g+1], ah[mt],  &bh[2]);
                    mma_bf16(c[mt][2*g],   ah[mt],  &bl[0]);
                    mma_bf16(c[mt][2*g+1], ah[mt],  &bl[2]);
                    mma_bf16(c[mt][2*g],   al2[mt], &bh[0]);
                    mma_bf16(c[mt][2*g+1], al2[mt], &bh[2]);
                }
            }
        }
        __syncthreads();
    }

    // epilogue
    const int crow = mrow0 + wr * 32 + (lane >> 2);
    const int ccol = n0 + wc * 64 + (lane & 3) * 2;
    #pragma unroll
    for (int mt = 0; mt < 2; mt++) {
        #pragma unroll
        for (int nt = 0; nt < 8; nt++) {
            int col = ccol + nt * 8;
            float b0 = 0.f, b1 = 0.f;
            if (bias) { b0 = bias[col]; b1 = bias[col + 1]; }
            int r0 = crow + mt * 16;
            if (r0 < M) {
                float2 v = make_float2(c[mt][nt][0] + b0, c[mt][nt][1] + b1);
                *(float2*)(Cb + (size_t)r0 * ldc + col) = v;
            }
            int r1 = r0 + 8;
            if (r1 < M) {
                float2 v = make_float2(c[mt][nt][2] + b0, c[mt][nt][3] + b1);
                *(float2*)(Cb + (size_t)r1 * ldc + col) = v;
            }
        }
    }
}

// ---------------------------------------------------------------------------
// Block reduction (sum, sumsq) over 256 threads
// ---------------------------------------------------------------------------
__device__ __forceinline__ void blockReduce2(float& s, float& q, float* red) {
    #pragma unroll
    for (int o = 16; o > 0; o >>= 1) {
        s += __shfl_xor_sync(0xffffffffu, s, o);
        q += __shfl_xor_sync(0xffffffffu, q, o);
    }
    const int t = threadIdx.x;
    if ((t & 31) == 0) { red[t >> 5] = s; red[8 + (t >> 5)] = q; }
    __syncthreads();
    s = 0.f; q = 0.f;
    #pragma unroll
    for (int i = 0; i < 8; i++) { s += red[i]; q += red[8 + i]; }
    __syncthreads();
}

// ---------------------------------------------------------------------------
// Fused middle: per (token, group); outputs Z as bf16 hi/lo
// ---------------------------------------------------------------------------
__global__ __launch_bounds__(256)
void midkernel(const float* __restrict__ x, const float* __restrict__ params,
               bf16* __restrict__ Zhi, bf16* __restrict__ Zlo)
{
    __shared__ float smem[12288];
    float* sX  = smem;
    float* sM  = smem + 2048;
    float* sS  = smem + 6144;
    float* sO1 = smem + 10240;
    float* red = smem;

    const int ng = blockIdx.x;
    const int t  = threadIdx.x;
    const float* xb = x + (size_t)ng * (INP * EIN);
    const float* pb = params + (size_t)(ng >> 2) * PCOLS + (size_t)(ng & 3) * TOTALP;

    {
        const float4* x4 = (const float4*)xb;
        const float4* m4 = (const float4*)pb;
        const float4* s4 = (const float4*)(pb + 4096);
        ((float4*)sX)[t]       = x4[t];
        ((float4*)sX)[t + 256] = x4[t + 256];
        #pragma unroll
        for (int i = 0; i < 4; i++) {
            ((float4*)sM)[t + 256 * i] = m4[t + 256 * i];
            ((float4*)sS)[t + 256 * i] = s4[t + 256 * i];
        }
    }
    __syncthreads();

    // stage 1: out1 = x[32,64] @ M[64,64]
    const int p1 = t >> 3;
    const int og = (t & 7) << 3;
    ull acc1[4] = {0ull, 0ull, 0ull, 0ull};
    #pragma unroll 4
    for (int cix = 0; cix < 64; cix++) {
        float xv = sX[p1 * 64 + cix];
        ull xv2 = pack2(xv, xv);
        const ulonglong2* mp = (const ulonglong2*)(sM + cix * 64 + og);
        ulonglong2 m0 = mp[0], m1 = mp[1];
        fma2(acc1[0], xv2, m0.x); fma2(acc1[1], xv2, m0.y);
        fma2(acc1[2], xv2, m1.x); fma2(acc1[3], xv2, m1.y);
    }
    float v1[8];
    unpack2(acc1[0], v1[0], v1[1]); unpack2(acc1[1], v1[2], v1[3]);
    unpack2(acc1[2], v1[4], v1[5]); unpack2(acc1[3], v1[6], v1[7]);
    float s1 = 0.f, q1 = 0.f;
    #pragma unroll
    for (int j = 0; j < 8; j++) { s1 += v1[j]; q1 += v1[j] * v1[j]; }
    __syncthreads();
    blockReduce2(s1, q1, red);
    {
        float mean = s1 * (1.f / 2048.f);
        float var  = q1 * (1.f / 2048.f) - mean * mean;
        float rs   = rsqrtf(var + 1e-5f);
        #pragma unroll
        for (int j = 0; j < 8; j++)
            sO1[p1 * 64 + og + j] = fmaxf((v1[j] - mean) * rs, 0.f);
    }
    __syncthreads();

    // stage 2: out2 = S[128,32] @ out1n[32,64]
    const int ty = t >> 3;
    const int tx = t & 7;
    ull acc2[4][4];
    #pragma unroll
    for (int i = 0; i < 4; i++)
        #pragma unroll
        for (int j = 0; j < 4; j++) acc2[i][j] = 0ull;

    #pragma unroll 4
    for (int p = 0; p < 32; p++) {
        const ulonglong2* op = (const ulonglong2*)(sO1 + p * 64 + tx * 8);
        ulonglong2 b0 = op[0], b1 = op[1];
        #pragma unroll
        for (int i = 0; i < 4; i++) {
            float sv = sS[(ty + 32 * i) * 32 + p];
            ull sv2 = pack2(sv, sv);
            fma2(acc2[i][0], sv2, b0.x); fma2(acc2[i][1], sv2, b0.y);
            fma2(acc2[i][2], sv2, b1.x); fma2(acc2[i][3], sv2, b1.y);
        }
    }
    float v2[4][8];
    float s2 = 0.f, q2 = 0.f;
    #pragma unroll
    for (int i = 0; i < 4; i++) {
        unpack2(acc2[i][0], v2[i][0], v2[i][1]); unpack2(acc2[i][1], v2[i][2], v2[i][3]);
        unpack2(acc2[i][2], v2[i][4], v2[i][5]); unpack2(acc2[i][3], v2[i][6], v2[i][7]);
        #pragma unroll
        for (int j = 0; j < 8; j++) { s2 += v2[i][j]; q2 += v2[i][j] * v2[i][j]; }
    }
    blockReduce2(s2, q2, red);
    float mean2 = s2 * (1.f / 8192.f);
    float var2  = q2 * (1.f / 8192.f) - mean2 * mean2;
    float rs2   = rsqrtf(var2 + 1e-5f);

    const size_t zbase = (size_t)(ng >> 2) * PCOLS + (size_t)(ng & 3) * TOTALP;
    #pragma unroll
    for (int i = 0; i < 4; i++) {
        const int qrow = ty + 32 * i;
        bf16 h[8], l[8];
        #pragma unroll
        for (int j = 0; j < 8; j++) {
            float o = fmaxf((v2[i][j] - mean2) * rs2, 0.f);
            f2hilo(o, h[j], l[j]);
        }
        size_t off = zbase + (size_t)qrow * 64 + tx * 8;
        *(uint4*)(Zhi + off) = make_uint4(bpk(h[0],h[1]), bpk(h[2],h[3]), bpk(h[4],h[5]), bpk(h[6],h[7]));
        *(uint4*)(Zlo + off) = make_uint4(bpk(l[0],l[1]), bpk(l[2],l[3]), bpk(l[4],l[5]), bpk(l[6],l[7]));
    }
}

// ---------------------------------------------------------------------------
__global__ void finalReduce(const float* __restrict__ part,
                            const float* __restrict__ query,
                            const float* __restrict__ bo,
                            float* __restrict__ out)
{
    int i = blockIdx.x * 256 + threadIdx.x;
    if (i >= NTOK * QDIM) return;
    float s = query[i] + bo[i & (QDIM - 1)];
    #pragma unroll
    for (int z = 0; z < SPLITK; z++)
        s += part[(size_t)z * NTOK * QDIM + i];
    out[i] = s;
}

// ---------------------------------------------------------------------------
extern "C" void kernel_launch(void* const* d_in, const int* in_sizes, int n_in,
                              void* d_out, int out_size)
{
    const float* x     = (const float*)d_in[0];
    const float* query = (const float*)d_in[1];
    const float* Wp    = (const float*)d_in[2];
    const float* bp    = (const float*)d_in[3];
    const float* Wo    = (const float*)d_in[4];
    const float* bo    = (const float*)d_in[5];
    float* out = (float*)d_out;

    float *pParams, *pPart;
    bf16 *pQh, *pQl, *pWpTh, *pWpTl, *pWoTh, *pWoTl, *pZh, *pZl;
    cudaGetSymbolAddress((void**)&pParams, g_params);
    cudaGetSymbolAddress((void**)&pPart, g_part);
    cudaGetSymbolAddress((void**)&pQh, g_qhi);
    cudaGetSymbolAddress((void**)&pQl, g_qlo);
    cudaGetSymbolAddress((void**)&pWpTh, g_wpT_hi);
    cudaGetSymbolAddress((void**)&pWpTl, g_wpT_lo);
    cudaGetSymbolAddress((void**)&pWoTh, g_woT_hi);
    cudaGetSymbolAddress((void**)&pWoTl, g_woT_lo);
    cudaGetSymbolAddress((void**)&pZh, g_zhi);
    cudaGetSymbolAddress((void**)&pZl, g_zlo);

    cudaFuncSetAttribute(gemm_mma, cudaFuncAttributeMaxDynamicSharedMemorySize, GSMEM);

    // conversions
    convQ<<<(NTOK * QDIM / 4 + 255) / 256, 256>>>(query, pQh, pQl);
    transConv<<<dim3(PCOLS / 32, QDIM / 32), dim3(32, 8)>>>(Wp, pWpTh, pWpTl, QDIM, PCOLS);
    transConv<<<dim3(QDIM / 32, PCOLS / 32), dim3(32, 8)>>>(Wo, pWoTh, pWoTl, PCOLS, QDIM);

    // GEMM1: params[3600,32768] = q @ Wp + bp   (K=256 -> 8 chunks of 32)
    gemm_mma<<<dim3(PCOLS / 128, 29, 1), 256, GSMEM>>>(
        pQh, pQl, pWpTh, pWpTl, pParams, bp,
        NTOK, QDIM, QDIM, PCOLS, 8, 0);

    // fused middle -> Z (bf16 hi/lo)
    midkernel<<<NTOK * 4, 256>>>(x, pParams, pZh, pZl);

    // GEMM3: part[z][3600,256] = Z[:, z*2048 : (z+1)*2048] @ Wo-chunk
    gemm_mma<<<dim3(QDIM / 128, 29, SPLITK), 256, GSMEM>>>(
        pZh, pZl, pWoTh, pWoTl, pPart, nullptr,
        NTOK, PCOLS, PCOLS, QDIM, (PCOLS / SPLITK) / 32, (int)((size_t)NTOK * QDIM));

    finalReduce<<<(NTOK * QDIM + 255) / 256, 256>>>(pPart, query, bo, out);
}

// round 5
// speedup vs baseline: 2.4699x; 1.1718x over previous
#include <cuda_runtime.h>
#include <cuda_bf16.h>
#include <cstdint>

// ---------------------------------------------------------------------------
// AdaptiveMixing on GB300 (compute_103 portable path):
//   params = query @ Wp + bp           [3600 x 32768]  (bf16-split mma.sync)
//   per (tok,grp): x@M -> LN -> relu -> S@ -> LN -> relu -> Z   (fp32 f32x2)
//   out = Z @ Wo + bo + query          [3600 x 256]    (bf16-split mma.sync)
// R5: midkernel re-blocked: 128 thr/CTA, 2x8 (stage1) and 8x8 (stage2)
//     register tiles -> 4x better fma2:LDS ratio in stage2.
// ---------------------------------------------------------------------------
#define NTOK   3600
#define QDIM   256
#define PCOLS  32768
#define TOTALP 8192
#define INP    32
#define EIN    64
#define SPLITK 16

typedef unsigned long long ull;
typedef __nv_bfloat16 bf16;

// ------------------------- device scratch (no allocs) ----------------------
__device__ float g_params[(size_t)NTOK * PCOLS];
__device__ bf16  g_qhi[(size_t)NTOK * QDIM];
__device__ bf16  g_qlo[(size_t)NTOK * QDIM];
__device__ bf16  g_wpT_hi[(size_t)PCOLS * QDIM];
__device__ bf16  g_wpT_lo[(size_t)PCOLS * QDIM];
__device__ bf16  g_woT_hi[(size_t)QDIM * PCOLS];
__device__ bf16  g_woT_lo[(size_t)QDIM * PCOLS];
__device__ bf16  g_zhi[(size_t)NTOK * PCOLS];
__device__ bf16  g_zlo[(size_t)NTOK * PCOLS];
__device__ float g_part[(size_t)SPLITK * NTOK * QDIM];

// ----------------------------- helpers -------------------------------------
__device__ __forceinline__ ull pack2(float lo, float hi) {
    ull r; asm("mov.b64 %0, {%1,%2};" : "=l"(r) : "f"(lo), "f"(hi)); return r;
}
__device__ __forceinline__ void unpack2(ull v, float& lo, float& hi) {
    asm("mov.b64 {%0,%1}, %2;" : "=f"(lo), "=f"(hi) : "l"(v));
}
__device__ __forceinline__ void fma2(ull& d, ull a, ull b) {
    asm("fma.rn.f32x2 %0, %1, %2, %0;" : "+l"(d) : "l"(a), "l"(b));
}
__device__ __forceinline__ void f2hilo(float v, bf16& h, bf16& l) {
    h = __float2bfloat16(v);
    l = __float2bfloat16(v - __bfloat162float(h));
}
__device__ __forceinline__ unsigned bpk(bf16 a, bf16 b) {
    return (unsigned)__bfloat16_as_ushort(a) | ((unsigned)__bfloat16_as_ushort(b) << 16);
}
__device__ __forceinline__ uint32_t smem_u32(const void* p) {
    uint32_t a;
    asm("{ .reg .u64 t; cvta.to.shared.u64 t, %1; cvt.u32.u64 %0, t; }" : "=r"(a) : "l"(p));
    return a;
}
__device__ __forceinline__ void ldsm4(uint32_t& r0, uint32_t& r1, uint32_t& r2, uint32_t& r3,
                                      uint32_t addr) {
    asm volatile("ldmatrix.sync.aligned.m8n8.x4.shared.b16 {%0,%1,%2,%3}, [%4];"
                 : "=r"(r0), "=r"(r1), "=r"(r2), "=r"(r3) : "r"(addr));
}
__device__ __forceinline__ void mma_bf16(float* c, const uint32_t* a, const uint32_t* b) {
    asm volatile(
        "mma.sync.aligned.m16n8k16.row.col.f32.bf16.bf16.f32 "
        "{%0,%1,%2,%3}, {%4,%5,%6,%7}, {%8,%9}, {%0,%1,%2,%3};"
        : "+f"(c[0]), "+f"(c[1]), "+f"(c[2]), "+f"(c[3])
        : "r"(a[0]), "r"(a[1]), "r"(a[2]), "r"(a[3]), "r"(b[0]), "r"(b[1]));
}
__device__ __forceinline__ void cpa16(uint32_t dst, const void* src, int sz) {
    asm volatile("cp.async.cg.shared.global [%0], [%1], 16, %2;"
                 :: "r"(dst), "l"(src), "r"(sz) : "memory");
}
#define CP_COMMIT() asm volatile("cp.async.commit_group;" ::: "memory")
#define CP_WAIT(n)  asm volatile("cp.async.wait_group %0;" :: "n"(n) : "memory")

// ---------------------------------------------------------------------------
// Conversion kernels
// ---------------------------------------------------------------------------
__global__ void convQ(const float* __restrict__ q, bf16* __restrict__ hi, bf16* __restrict__ lo) {
    int i = blockIdx.x * 256 + threadIdx.x;
    if (i >= NTOK * QDIM / 4) return;
    float4 v = ((const float4*)q)[i];
    bf16 h0,l0,h1,l1,h2,l2,h3,l3;
    f2hilo(v.x,h0,l0); f2hilo(v.y,h1,l1); f2hilo(v.z,h2,l2); f2hilo(v.w,h3,l3);
    ((uint2*)hi)[i] = make_uint2(bpk(h0,h1), bpk(h2,h3));
    ((uint2*)lo)[i] = make_uint2(bpk(l0,l1), bpk(l2,l3));
}

// transpose + split: in [R][C] f32 -> out[C][R] bf16 hi/lo
__global__ void transConv(const float* __restrict__ in, bf16* __restrict__ oHi,
                          bf16* __restrict__ oLo, int R, int C) {
    __shared__ float tile[32][33];
    int c0 = blockIdx.x * 32, r0 = blockIdx.y * 32;
    int tx = threadIdx.x, ty = threadIdx.y;    // 32 x 8
    #pragma unroll
    for (int i = 0; i < 4; i++)
        tile[ty + 8 * i][tx] = in[(size_t)(r0 + ty + 8 * i) * C + c0 + tx];
    __syncthreads();
    #pragma unroll
    for (int i = 0; i < 4; i++) {
        float v = tile[tx][ty + 8 * i];
        bf16 h, l; f2hilo(v, h, l);
        size_t o = (size_t)(c0 + ty + 8 * i) * R + r0 + tx;
        oHi[o] = h; oLo[o] = l;
    }
}

// ---------------------------------------------------------------------------
// bf16-split GEMM via mma.sync (same as R4)
// ---------------------------------------------------------------------------
#define TILE_B   10240
#define STAGE_B  (4 * TILE_B)
#define GSMEM    (2 * STAGE_B)

__global__ __launch_bounds__(256, 2)
void gemm_mma(const bf16* __restrict__ Ahi, const bf16* __restrict__ Alo,
              const bf16* __restrict__ Bhi, const bf16* __restrict__ Blo,
              float* __restrict__ C, const float* __restrict__ bias,
              int M, int lda, int ldb, int ldc, int nChunks, int partStride)
{
    extern __shared__ char smem[];
    const uint32_t sm0 = smem_u32(smem);
    const int t = threadIdx.x, lane = t & 31, w = t >> 5;
    const int wr = w & 3, wc = w >> 2;
    const int mrow0 = blockIdx.y * 128;
    const int n0 = blockIdx.x * 128;
    const int k0 = blockIdx.z * nChunks * 32;
    float* Cb = C + (size_t)blockIdx.z * partStride;

    const int row0_ = t >> 2, seg0 = t & 3;
    const int row1_ = (t + 256) >> 2, seg1 = (t + 256) & 3;
    const uint32_t so0 = (uint32_t)(row0_ * 40 + seg0 * 8) * 2;
    const uint32_t so1 = (uint32_t)(row1_ * 40 + seg1 * 8) * 2;
    const int okA0 = ((mrow0 + row0_) < M) ? 16 : 0;
    const int okA1 = ((mrow0 + row1_) < M) ? 16 : 0;
    const size_t gaBase0 = (size_t)(mrow0 + row0_) * lda + seg0 * 8;
    const size_t gaBase1 = (size_t)(mrow0 + row1_) * lda + seg1 * 8;
    const size_t gbBase0 = (size_t)(n0 + row0_) * ldb + seg0 * 8;
    const size_t gbBase1 = (size_t)(n0 + row1_) * ldb + seg1 * 8;

    const int q = lane >> 3, r8 = lane & 7;
    const uint32_t aoff = (uint32_t)((wr * 32 + r8 + ((q & 1) << 3)) * 40 + ((q >> 1) << 3)) * 2;
    const uint32_t boff = (uint32_t)((wc * 64 + r8 + ((q >> 1) << 3)) * 40 + ((q & 1) << 3)) * 2;

    float c[2][8][4];
    #pragma unroll
    for (int mt = 0; mt < 2; mt++)
        #pragma unroll
        for (int nt = 0; nt < 8; nt++)
            #pragma unroll
            for (int j = 0; j < 4; j++) c[mt][nt][j] = 0.f;

    auto stageLoad = [&](int stage, int kk) {
        uint32_t sb = sm0 + stage * STAGE_B;
        cpa16(sb + 0 * TILE_B + so0, Ahi + gaBase0 + kk, okA0);
        cpa16(sb + 1 * TILE_B + so0, Alo + gaBase0 + kk, okA0);
        cpa16(sb + 2 * TILE_B + so0, Bhi + gbBase0 + kk, 16);
        cpa16(sb + 3 * TILE_B + so0, Blo + gbBase0 + kk, 16);
        cpa16(sb + 0 * TILE_B + so1, Ahi + gaBase1 + kk, okA1);
        cpa16(sb + 1 * TILE_B + so1, Alo + gaBase1 + kk, okA1);
        cpa16(sb + 2 * TILE_B + so1, Bhi + gbBase1 + kk, 16);
        cpa16(sb + 3 * TILE_B + so1, Blo + gbBase1 + kk, 16);
        CP_COMMIT();
    };

    stageLoad(0, k0);

    for (int ch = 0; ch < nChunks; ch++) {
        const int st = ch & 1;
        const bool more = (ch + 1) < nChunks;
        if (more) stageLoad(st ^ 1, k0 + (ch + 1) * 32);
        if (more) { CP_WAIT(1); } else { CP_WAIT(0); }
        __syncthreads();

        const uint32_t base = sm0 + st * STAGE_B;
        #pragma unroll
        for (int ks = 0; ks < 2; ks++) {
            uint32_t ah[2][4], al2[2][4];
            #pragma unroll
            for (int mt = 0; mt < 2; mt++) {
                uint32_t aA = base + aoff + mt * (16 * 80) + ks * 32;
                ldsm4(ah[mt][0], ah[mt][1], ah[mt][2], ah[mt][3], aA);
                ldsm4(al2[mt][0], al2[mt][1], al2[mt][2], al2[mt][3], aA + TILE_B);
            }
            #pragma unroll
            for (int g = 0; g < 4; g++) {
                uint32_t bh[4], bl[4];
                uint32_t aB = base + 2 * TILE_B + boff + g * (16 * 80) + ks * 32;
                ldsm4(bh[0], bh[1], bh[2], bh[3], aB);
                ldsm4(bl[0], bl[1], bl[2], bl[3], aB + TILE_B);
                #pragma unroll
                for (int mt = 0; mt < 2; mt++) {
                    mma_bf16(c[mt][2*g],   ah[mt],  &bh[0]);
                    mma_bf16(c[mt][2*g+1], ah[mt],  &bh[2]);
                    mma_bf16(c[mt][2*g],   ah[mt],  &bl[0]);
                    mma_bf16(c[mt][2*g+1], ah[mt],  &bl[2]);
                    mma_bf16(c[mt][2*g],   al2[mt], &bh[0]);
                    mma_bf16(c[mt][2*g+1], al2[mt], &bh[2]);
                }
            }
        }
        __syncthreads();
    }

    const int crow = mrow0 + wr * 32 + (lane >> 2);
    const int ccol = n0 + wc * 64 + (lane & 3) * 2;
    #pragma unroll
    for (int mt = 0; mt < 2; mt++) {
        #pragma unroll
        for (int nt = 0; nt < 8; nt++) {
            int col = ccol + nt * 8;
            float b0 = 0.f, b1 = 0.f;
            if (bias) { b0 = bias[col]; b1 = bias[col + 1]; }
            int r0 = crow + mt * 16;
            if (r0 < M) {
                float2 v = make_float2(c[mt][nt][0] + b0, c[mt][nt][1] + b1);
                *(float2*)(Cb + (size_t)r0 * ldc + col) = v;
            }
            int r1 = r0 + 8;
            if (r1 < M) {
                float2 v = make_float2(c[mt][nt][2] + b0, c[mt][nt][3] + b1);
                *(float2*)(Cb + (size_t)r1 * ldc + col) = v;
            }
        }
    }
}

// ---------------------------------------------------------------------------
// Block reduction of (sum, sumsq) over 128 threads / 4 warps.
// ---------------------------------------------------------------------------
__device__ __forceinline__ void blockReduce2_128(float& s, float& q, float* red) {
    #pragma unroll
    for (int o = 16; o > 0; o >>= 1) {
        s += __shfl_xor_sync(0xffffffffu, s, o);
        q += __shfl_xor_sync(0xffffffffu, q, o);
    }
    const int t = threadIdx.x;
    if ((t & 31) == 0) { red[t >> 5] = s; red[4 + (t >> 5)] = q; }
    __syncthreads();
    s = red[0] + red[1] + red[2] + red[3];
    q = red[4] + red[5] + red[6] + red[7];
    __syncthreads();
}

// ---------------------------------------------------------------------------
// Fused middle v2: 128 threads per (token, group) CTA; register-blocked.
//   stage1: thread -> 2 rows x 8 cols of out1 (32x64)
//   stage2: thread -> 8 q-rows x 8 cols of out2 (128x64)
// ---------------------------------------------------------------------------
__global__ __launch_bounds__(128)
void midkernel(const float* __restrict__ x, const float* __restrict__ params,
               bf16* __restrict__ Zhi, bf16* __restrict__ Zlo)
{
    __shared__ float smem[12288];          // 48 KB
    float* sX  = smem;                     // [32][64]  2048
    float* sM  = smem + 2048;              // [64][64]  4096
    float* sS  = smem + 6144;              // [128][32] 4096
    float* sO1 = smem + 10240;             // [32][64]  2048
    float* red = smem;                     // overlays sX after stage1

    const int ng = blockIdx.x;
    const int t  = threadIdx.x;            // 0..127
    const float* xb = x + (size_t)ng * (INP * EIN);
    const float* pb = params + (size_t)(ng >> 2) * PCOLS + (size_t)(ng & 3) * TOTALP;

    {   // cooperative loads: 128 threads
        const float4* x4 = (const float4*)xb;
        const float4* m4 = (const float4*)pb;
        const float4* s4 = (const float4*)(pb + 4096);
        ((float4*)sX)[t]       = x4[t];
        ((float4*)sX)[t + 128] = x4[t + 128];
        ((float4*)sX)[t + 256] = x4[t + 256];
        ((float4*)sX)[t + 384] = x4[t + 384];
        #pragma unroll
        for (int i = 0; i < 8; i++) {
            ((float4*)sM)[t + 128 * i] = m4[t + 128 * i];
            ((float4*)sS)[t + 128 * i] = s4[t + 128 * i];
        }
    }
    __syncthreads();

    // ---- stage 1: out1[p][o] = sum_c x[p][c]*M[c][o]; 2 rows x 8 cols ----
    const int p0 = (t >> 3) << 1;          // 0,2,...,30
    const int og = (t & 7) << 3;           // 0..56
    ull acc1[2][4];
    #pragma unroll
    for (int i = 0; i < 2; i++)
        #pragma unroll
        for (int j = 0; j < 4; j++) acc1[i][j] = 0ull;

    #pragma unroll 4
    for (int cix = 0; cix < 64; cix++) {
        float xv0 = sX[p0 * 64 + cix];
        float xv1 = sX[(p0 + 1) * 64 + cix];
        ull x0 = pack2(xv0, xv0);
        ull x1 = pack2(xv1, xv1);
        const ulonglong2* mp = (const ulonglong2*)(sM + cix * 64 + og);
        ulonglong2 m0 = mp[0], m1 = mp[1];
        fma2(acc1[0][0], x0, m0.x); fma2(acc1[0][1], x0, m0.y);
        fma2(acc1[0][2], x0, m1.x); fma2(acc1[0][3], x0, m1.y);
        fma2(acc1[1][0], x1, m0.x); fma2(acc1[1][1], x1, m0.y);
        fma2(acc1[1][2], x1, m1.x); fma2(acc1[1][3], x1, m1.y);
    }
    float v1[2][8];
    float s1 = 0.f, q1 = 0.f;
    #pragma unroll
    for (int i = 0; i < 2; i++) {
        unpack2(acc1[i][0], v1[i][0], v1[i][1]); unpack2(acc1[i][1], v1[i][2], v1[i][3]);
        unpack2(acc1[i][2], v1[i][4], v1[i][5]); unpack2(acc1[i][3], v1[i][6], v1[i][7]);
        #pragma unroll
        for (int j = 0; j < 8; j++) { s1 += v1[i][j]; q1 += v1[i][j] * v1[i][j]; }
    }
    __syncthreads();                       // sX reads done before red overlay
    blockReduce2_128(s1, q1, red);
    {
        float mean = s1 * (1.f / 2048.f);
        float var  = q1 * (1.f / 2048.f) - mean * mean;
        float rs   = rsqrtf(var + 1e-5f);
        #pragma unroll
        for (int i = 0; i < 2; i++)
            #pragma unroll
            for (int j = 0; j < 8; j++)
                sO1[(p0 + i) * 64 + og + j] = fmaxf((v1[i][j] - mean) * rs, 0.f);
    }
    __syncthreads();

    // ---- stage 2: out2[q][o] = sum_p S[q][p]*out1n[p][o]; 8 rows x 8 cols --
    const int ty = t >> 3;                 // 0..15 -> q rows ty+16*i
    const int tx = t & 7;                  // col block tx*8
    ull acc2[8][4];
    #pragma unroll
    for (int i = 0; i < 8; i++)
        #pragma unroll
        for (int j = 0; j < 4; j++) acc2[i][j] = 0ull;

    #pragma unroll 2
    for (int p = 0; p < 32; p++) {
        const ulonglong2* op = (const ulonglong2*)(sO1 + p * 64 + tx * 8);
        ulonglong2 b0 = op[0], b1 = op[1];
        #pragma unroll
        for (int i = 0; i < 8; i++) {
            float sv = sS[(ty + 16 * i) * 32 + p];
            ull sv2 = pack2(sv, sv);
            fma2(acc2[i][0], sv2, b0.x); fma2(acc2[i][1], sv2, b0.y);
            fma2(acc2[i][2], sv2, b1.x); fma2(acc2[i][3], sv2, b1.y);
        }
    }
    float v2[8][8];
    float s2 = 0.f, q2 = 0.f;
    #pragma unroll
    for (int i = 0; i < 8; i++) {
        unpack2(acc2[i][0], v2[i][0], v2[i][1]); unpack2(acc2[i][1], v2[i][2], v2[i][3]);
        unpack2(acc2[i][2], v2[i][4], v2[i][5]); unpack2(acc2[i][3], v2[i][6], v2[i][7]);
        #pragma unroll
        for (int j = 0; j < 8; j++) { s2 += v2[i][j]; q2 += v2[i][j] * v2[i][j]; }
    }
    blockReduce2_128(s2, q2, red);
    float mean2 = s2 * (1.f / 8192.f);
    float var2  = q2 * (1.f / 8192.f) - mean2 * mean2;
    float rs2   = rsqrtf(var2 + 1e-5f);

    const size_t zbase = (size_t)(ng >> 2) * PCOLS + (size_t)(ng & 3) * TOTALP;
    #pragma unroll
    for (int i = 0; i < 8; i++) {
        const int qrow = ty + 16 * i;
        bf16 h[8], l[8];
        #pragma unroll
        for (int j = 0; j < 8; j++) {
            float o = fmaxf((v2[i][j] - mean2) * rs2, 0.f);
            f2hilo(o, h[j], l[j]);
        }
        size_t off = zbase + (size_t)qrow * 64 + tx * 8;
        *(uint4*)(Zhi + off) = make_uint4(bpk(h[0],h[1]), bpk(h[2],h[3]), bpk(h[4],h[5]), bpk(h[6],h[7]));
        *(uint4*)(Zlo + off) = make_uint4(bpk(l[0],l[1]), bpk(l[2],l[3]), bpk(l[4],l[5]), bpk(l[6],l[7]));
    }
}

// ---------------------------------------------------------------------------
__global__ void finalReduce(const float* __restrict__ part,
                            const float* __restrict__ query,
                            const float* __restrict__ bo,
                            float* __restrict__ out)
{
    int i = blockIdx.x * 256 + threadIdx.x;
    if (i >= NTOK * QDIM) return;
    float s = query[i] + bo[i & (QDIM - 1)];
    #pragma unroll
    for (int z = 0; z < SPLITK; z++)
        s += part[(size_t)z * NTOK * QDIM + i];
    out[i] = s;
}

// ---------------------------------------------------------------------------
extern "C" void kernel_launch(void* const* d_in, const int* in_sizes, int n_in,
                              void* d_out, int out_size)
{
    const float* x     = (const float*)d_in[0];
    const float* query = (const float*)d_in[1];
    const float* Wp    = (const float*)d_in[2];
    const float* bp    = (const float*)d_in[3];
    const float* Wo    = (const float*)d_in[4];
    const float* bo    = (const float*)d_in[5];
    float* out = (float*)d_out;

    float *pParams, *pPart;
    bf16 *pQh, *pQl, *pWpTh, *pWpTl, *pWoTh, *pWoTl, *pZh, *pZl;
    cudaGetSymbolAddress((void**)&pParams, g_params);
    cudaGetSymbolAddress((void**)&pPart, g_part);
    cudaGetSymbolAddress((void**)&pQh, g_qhi);
    cudaGetSymbolAddress((void**)&pQl, g_qlo);
    cudaGetSymbolAddress((void**)&pWpTh, g_wpT_hi);
    cudaGetSymbolAddress((void**)&pWpTl, g_wpT_lo);
    cudaGetSymbolAddress((void**)&pWoTh, g_woT_hi);
    cudaGetSymbolAddress((void**)&pWoTl, g_woT_lo);
    cudaGetSymbolAddress((void**)&pZh, g_zhi);
    cudaGetSymbolAddress((void**)&pZl, g_zlo);

    cudaFuncSetAttribute(gemm_mma, cudaFuncAttributeMaxDynamicSharedMemorySize, GSMEM);

    // conversions
    convQ<<<(NTOK * QDIM / 4 + 255) / 256, 256>>>(query, pQh, pQl);
    transConv<<<dim3(PCOLS / 32, QDIM / 32), dim3(32, 8)>>>(Wp, pWpTh, pWpTl, QDIM, PCOLS);
    transConv<<<dim3(QDIM / 32, PCOLS / 32), dim3(32, 8)>>>(Wo, pWoTh, pWoTl, PCOLS, QDIM);

    // GEMM1: params[3600,32768] = q @ Wp + bp   (K=256 -> 8 chunks of 32)
    gemm_mma<<<dim3(PCOLS / 128, 29, 1), 256, GSMEM>>>(
        pQh, pQl, pWpTh, pWpTl, pParams, bp,
        NTOK, QDIM, QDIM, PCOLS, 8, 0);

    // fused middle -> Z (bf16 hi/lo)
    midkernel<<<NTOK * 4, 128>>>(x, pParams, pZh, pZl);

    // GEMM3: part[z][3600,256] = Z[:, z*2048 : (z+1)*2048] @ Wo-chunk
    gemm_mma<<<dim3(QDIM / 128, 29, SPLITK), 256, GSMEM>>>(
        pZh, pZl, pWoTh, pWoTl, pPart, nullptr,
        NTOK, PCOLS, PCOLS, QDIM, (PCOLS / SPLITK) / 32, (int)((size_t)NTOK * QDIM));

    finalReduce<<<(NTOK * QDIM + 255) / 256, 256>>>(pPart, query, bo, out);
}

// round 6
// speedup vs baseline: 2.7530x; 1.1146x over previous
#include <cuda_runtime.h>
#include <cuda_bf16.h>
#include <cstdint>

// ---------------------------------------------------------------------------
// AdaptiveMixing on GB300 (compute_103 portable path):
//   params = query @ Wp + bp           [3600 x 32768]  (bf16-split mma.sync)
//   per (tok,grp): x@M -> LN -> relu -> S@ -> LN -> relu -> Z   (fp32 f32x2)
//   out = Z @ Wo + bo + query          [3600 x 256]    (bf16-split mma.sync)
// R6: mid stage-2 uses transposed-S smem (vector LDS), conversions overlap
//     on side streams, GEMM3 SPLITK 32 for wave smoothing.
// ---------------------------------------------------------------------------
#define NTOK   3600
#define QDIM   256
#define PCOLS  32768
#define TOTALP 8192
#define INP    32
#define EIN    64
#define SPLITK 32

typedef unsigned long long ull;
typedef __nv_bfloat16 bf16;

// ------------------------- device scratch (no allocs) ----------------------
__device__ float g_params[(size_t)NTOK * PCOLS];
__device__ bf16  g_qhi[(size_t)NTOK * QDIM];
__device__ bf16  g_qlo[(size_t)NTOK * QDIM];
__device__ bf16  g_wpT_hi[(size_t)PCOLS * QDIM];
__device__ bf16  g_wpT_lo[(size_t)PCOLS * QDIM];
__device__ bf16  g_woT_hi[(size_t)QDIM * PCOLS];
__device__ bf16  g_woT_lo[(size_t)QDIM * PCOLS];
__device__ bf16  g_zhi[(size_t)NTOK * PCOLS];
__device__ bf16  g_zlo[(size_t)NTOK * PCOLS];
__device__ float g_part[(size_t)SPLITK * NTOK * QDIM];

// ----------------------------- helpers -------------------------------------
__device__ __forceinline__ ull pack2(float lo, float hi) {
    ull r; asm("mov.b64 %0, {%1,%2};" : "=l"(r) : "f"(lo), "f"(hi)); return r;
}
__device__ __forceinline__ void unpack2(ull v, float& lo, float& hi) {
    asm("mov.b64 {%0,%1}, %2;" : "=f"(lo), "=f"(hi) : "l"(v));
}
__device__ __forceinline__ void fma2(ull& d, ull a, ull b) {
    asm("fma.rn.f32x2 %0, %1, %2, %0;" : "+l"(d) : "l"(a), "l"(b));
}
__device__ __forceinline__ void f2hilo(float v, bf16& h, bf16& l) {
    h = __float2bfloat16(v);
    l = __float2bfloat16(v - __bfloat162float(h));
}
__device__ __forceinline__ unsigned bpk(bf16 a, bf16 b) {
    return (unsigned)__bfloat16_as_ushort(a) | ((unsigned)__bfloat16_as_ushort(b) << 16);
}
__device__ __forceinline__ uint32_t smem_u32(const void* p) {
    uint32_t a;
    asm("{ .reg .u64 t; cvta.to.shared.u64 t, %1; cvt.u32.u64 %0, t; }" : "=r"(a) : "l"(p));
    return a;
}
__device__ __forceinline__ void ldsm4(uint32_t& r0, uint32_t& r1, uint32_t& r2, uint32_t& r3,
                                      uint32_t addr) {
    asm volatile("ldmatrix.sync.aligned.m8n8.x4.shared.b16 {%0,%1,%2,%3}, [%4];"
                 : "=r"(r0), "=r"(r1), "=r"(r2), "=r"(r3) : "r"(addr));
}
__device__ __forceinline__ void mma_bf16(float* c, const uint32_t* a, const uint32_t* b) {
    asm volatile(
        "mma.sync.aligned.m16n8k16.row.col.f32.bf16.bf16.f32 "
        "{%0,%1,%2,%3}, {%4,%5,%6,%7}, {%8,%9}, {%0,%1,%2,%3};"
        : "+f"(c[0]), "+f"(c[1]), "+f"(c[2]), "+f"(c[3])
        : "r"(a[0]), "r"(a[1]), "r"(a[2]), "r"(a[3]), "r"(b[0]), "r"(b[1]));
}
__device__ __forceinline__ void cpa16(uint32_t dst, const void* src, int sz) {
    asm volatile("cp.async.cg.shared.global [%0], [%1], 16, %2;"
                 :: "r"(dst), "l"(src), "r"(sz) : "memory");
}
#define CP_COMMIT() asm volatile("cp.async.commit_group;" ::: "memory")
#define CP_WAIT(n)  asm volatile("cp.async.wait_group %0;" :: "n"(n) : "memory")

// ---------------------------------------------------------------------------
// Conversion kernels
// ---------------------------------------------------------------------------
__global__ void convQ(const float* __restrict__ q, bf16* __restrict__ hi, bf16* __restrict__ lo) {
    int i = blockIdx.x * 256 + threadIdx.x;
    if (i >= NTOK * QDIM / 4) return;
    float4 v = ((const float4*)q)[i];
    bf16 h0,l0,h1,l1,h2,l2,h3,l3;
    f2hilo(v.x,h0,l0); f2hilo(v.y,h1,l1); f2hilo(v.z,h2,l2); f2hilo(v.w,h3,l3);
    ((uint2*)hi)[i] = make_uint2(bpk(h0,h1), bpk(h2,h3));
    ((uint2*)lo)[i] = make_uint2(bpk(l0,l1), bpk(l2,l3));
}

// transpose + split: in [R][C] f32 -> out[C][R] bf16 hi/lo
__global__ void transConv(const float* __restrict__ in, bf16* __restrict__ oHi,
                          bf16* __restrict__ oLo, int R, int C) {
    __shared__ float tile[32][33];
    int c0 = blockIdx.x * 32, r0 = blockIdx.y * 32;
    int tx = threadIdx.x, ty = threadIdx.y;    // 32 x 8
    #pragma unroll
    for (int i = 0; i < 4; i++)
        tile[ty + 8 * i][tx] = in[(size_t)(r0 + ty + 8 * i) * C + c0 + tx];
    __syncthreads();
    #pragma unroll
    for (int i = 0; i < 4; i++) {
        float v = tile[tx][ty + 8 * i];
        bf16 h, l; f2hilo(v, h, l);
        size_t o = (size_t)(c0 + ty + 8 * i) * R + r0 + tx;
        oHi[o] = h; oLo[o] = l;
    }
}

// ---------------------------------------------------------------------------
// bf16-split GEMM via mma.sync (same as R4/R5)
// ---------------------------------------------------------------------------
#define TILE_B   10240
#define STAGE_B  (4 * TILE_B)
#define GSMEM    (2 * STAGE_B)

__global__ __launch_bounds__(256, 2)
void gemm_mma(const bf16* __restrict__ Ahi, const bf16* __restrict__ Alo,
              const bf16* __restrict__ Bhi, const bf16* __restrict__ Blo,
              float* __restrict__ C, const float* __restrict__ bias,
              int M, int lda, int ldb, int ldc, int nChunks, int partStride)
{
    extern __shared__ char smem[];
    const uint32_t sm0 = smem_u32(smem);
    const int t = threadIdx.x, lane = t & 31, w = t >> 5;
    const int wr = w & 3, wc = w >> 2;
    const int mrow0 = blockIdx.y * 128;
    const int n0 = blockIdx.x * 128;
    const int k0 = blockIdx.z * nChunks * 32;
    float* Cb = C + (size_t)blockIdx.z * partStride;

    const int row0_ = t >> 2, seg0 = t & 3;
    const int row1_ = (t + 256) >> 2, seg1 = (t + 256) & 3;
    const uint32_t so0 = (uint32_t)(row0_ * 40 + seg0 * 8) * 2;
    const uint32_t so1 = (uint32_t)(row1_ * 40 + seg1 * 8) * 2;
    const int okA0 = ((mrow0 + row0_) < M) ? 16 : 0;
    const int okA1 = ((mrow0 + row1_) < M) ? 16 : 0;
    const size_t gaBase0 = (size_t)(mrow0 + row0_) * lda + seg0 * 8;
    const size_t gaBase1 = (size_t)(mrow0 + row1_) * lda + seg1 * 8;
    const size_t gbBase0 = (size_t)(n0 + row0_) * ldb + seg0 * 8;
    const size_t gbBase1 = (size_t)(n0 + row1_) * ldb + seg1 * 8;

    const int q = lane >> 3, r8 = lane & 7;
    const uint32_t aoff = (uint32_t)((wr * 32 + r8 + ((q & 1) << 3)) * 40 + ((q >> 1) << 3)) * 2;
    const uint32_t boff = (uint32_t)((wc * 64 + r8 + ((q >> 1) << 3)) * 40 + ((q & 1) << 3)) * 2;

    float c[2][8][4];
    #pragma unroll
    for (int mt = 0; mt < 2; mt++)
        #pragma unroll
        for (int nt = 0; nt < 8; nt++)
            #pragma unroll
            for (int j = 0; j < 4; j++) c[mt][nt][j] = 0.f;

    auto stageLoad = [&](int stage, int kk) {
        uint32_t sb = sm0 + stage * STAGE_B;
        cpa16(sb + 0 * TILE_B + so0, Ahi + gaBase0 + kk, okA0);
        cpa16(sb + 1 * TILE_B + so0, Alo + gaBase0 + kk, okA0);
        cpa16(sb + 2 * TILE_B + so0, Bhi + gbBase0 + kk, 16);
        cpa16(sb + 3 * TILE_B + so0, Blo + gbBase0 + kk, 16);
        cpa16(sb + 0 * TILE_B + so1, Ahi + gaBase1 + kk, okA1);
        cpa16(sb + 1 * TILE_B + so1, Alo + gaBase1 + kk, okA1);
        cpa16(sb + 2 * TILE_B + so1, Bhi + gbBase1 + kk, 16);
        cpa16(sb + 3 * TILE_B + so1, Blo + gbBase1 + kk, 16);
        CP_COMMIT();
    };

    stageLoad(0, k0);

    for (int ch = 0; ch < nChunks; ch++) {
        const int st = ch & 1;
        const bool more = (ch + 1) < nChunks;
        if (more) stageLoad(st ^ 1, k0 + (ch + 1) * 32);
        if (more) { CP_WAIT(1); } else { CP_WAIT(0); }
        __syncthreads();

        const uint32_t base = sm0 + st * STAGE_B;
        #pragma unroll
        for (int ks = 0; ks < 2; ks++) {
            uint32_t ah[2][4], al2[2][4];
            #pragma unroll
            for (int mt = 0; mt < 2; mt++) {
                uint32_t aA = base + aoff + mt * (16 * 80) + ks * 32;
                ldsm4(ah[mt][0], ah[mt][1], ah[mt][2], ah[mt][3], aA);
                ldsm4(al2[mt][0], al2[mt][1], al2[mt][2], al2[mt][3], aA + TILE_B);
            }
            #pragma unroll
            for (int g = 0; g < 4; g++) {
                uint32_t bh[4], bl[4];
                uint32_t aB = base + 2 * TILE_B + boff + g * (16 * 80) + ks * 32;
                ldsm4(bh[0], bh[1], bh[2], bh[3], aB);
                ldsm4(bl[0], bl[1], bl[2], bl[3], aB + TILE_B);
                #pragma unroll
                for (int mt = 0; mt < 2; mt++) {
                    mma_bf16(c[mt][2*g],   ah[mt],  &bh[0]);
                    mma_bf16(c[mt][2*g+1], ah[mt],  &bh[2]);
                    mma_bf16(c[mt][2*g],   ah[mt],  &bl[0]);
                    mma_bf16(c[mt][2*g+1], ah[mt],  &bl[2]);
                    mma_bf16(c[mt][2*g],   al2[mt], &bh[0]);
                    mma_bf16(c[mt][2*g+1], al2[mt], &bh[2]);
                }
            }
        }
        __syncthreads();
    }

    const int crow = mrow0 + wr * 32 + (lane >> 2);
    const int ccol = n0 + wc * 64 + (lane & 3) * 2;
    #pragma unroll
    for (int mt = 0; mt < 2; mt++) {
        #pragma unroll
        for (int nt = 0; nt < 8; nt++) {
            int col = ccol + nt * 8;
            float b0 = 0.f, b1 = 0.f;
            if (bias) { b0 = bias[col]; b1 = bias[col + 1]; }
            int r0 = crow + mt * 16;
            if (r0 < M) {
                float2 v = make_float2(c[mt][nt][0] + b0, c[mt][nt][1] + b1);
                *(float2*)(Cb + (size_t)r0 * ldc + col) = v;
            }
            int r1 = r0 + 8;
            if (r1 < M) {
                float2 v = make_float2(c[mt][nt][2] + b0, c[mt][nt][3] + b1);
                *(float2*)(Cb + (size_t)r1 * ldc + col) = v;
            }
        }
    }
}

// ---------------------------------------------------------------------------
// Block reduction of (sum, sumsq) over 128 threads / 4 warps.
// ---------------------------------------------------------------------------
__device__ __forceinline__ void blockReduce2_128(float& s, float& q, float* red) {
    #pragma unroll
    for (int o = 16; o > 0; o >>= 1) {
        s += __shfl_xor_sync(0xffffffffu, s, o);
        q += __shfl_xor_sync(0xffffffffu, q, o);
    }
    const int t = threadIdx.x;
    if ((t & 31) == 0) { red[t >> 5] = s; red[4 + (t >> 5)] = q; }
    __syncthreads();
    s = red[0] + red[1] + red[2] + red[3];
    q = red[4] + red[5] + red[6] + red[7];
    __syncthreads();
}

// ---------------------------------------------------------------------------
// Fused middle v3: 128 threads/CTA; stage2 uses transposed S in smem so the
// hot loop is 4x LDS.128 (broadcast, conflict-free) per 32 fma2.
//   stage1: thread -> 2 rows x 8 cols of out1 (32x64)
//   stage2: thread -> 8 consecutive q-rows x 8 cols of out2 (128x64)
// ---------------------------------------------------------------------------
__global__ __launch_bounds__(128)
void midkernel(const float* __restrict__ x, const float* __restrict__ params,
               bf16* __restrict__ Zhi, bf16* __restrict__ Zlo)
{
    __shared__ float smem[12288];          // 48 KB
    float* sX  = smem;                     // [32][64]   2048
    float* sM  = smem + 2048;              // [64][64]   4096
    float* sST = smem + 6144;              // [32][128]  4096 (S transposed)
    float* sO1 = smem + 10240;             // [32][64]   2048
    float* red = smem;                     // overlays sX after stage1

    const int ng = blockIdx.x;
    const int t  = threadIdx.x;            // 0..127
    const float* xb = x + (size_t)ng * (INP * EIN);
    const float* pb = params + (size_t)(ng >> 2) * PCOLS + (size_t)(ng & 3) * TOTALP;

    {   // cooperative loads
        const float4* x4 = (const float4*)xb;
        const float4* m4 = (const float4*)pb;
        const float4* s4 = (const float4*)(pb + 4096);
        ((float4*)sX)[t]       = x4[t];
        ((float4*)sX)[t + 128] = x4[t + 128];
        ((float4*)sX)[t + 256] = x4[t + 256];
        ((float4*)sX)[t + 384] = x4[t + 384];
        #pragma unroll
        for (int i = 0; i < 8; i++)
            ((float4*)sM)[t + 128 * i] = m4[t + 128 * i];
        // S: [128 q][32 p] -> sST[p][q]
        #pragma unroll
        for (int i = 0; i < 8; i++) {
            int idx = t + 128 * i;
            float4 v = s4[idx];
            int qq = idx >> 3;             // row (8 float4 per 32-col row)
            int p4 = (idx & 7) << 2;       // p base
            sST[(p4 + 0) * 128 + qq] = v.x;
            sST[(p4 + 1) * 128 + qq] = v.y;
            sST[(p4 + 2) * 128 + qq] = v.z;
            sST[(p4 + 3) * 128 + qq] = v.w;
        }
    }
    __syncthreads();

    // ---- stage 1: out1[p][o] = sum_c x[p][c]*M[c][o]; 2 rows x 8 cols ----
    const int p0 = (t >> 3) << 1;
    const int og = (t & 7) << 3;
    ull acc1[2][4];
    #pragma unroll
    for (int i = 0; i < 2; i++)
        #pragma unroll
        for (int j = 0; j < 4; j++) acc1[i][j] = 0ull;

    #pragma unroll 4
    for (int cix = 0; cix < 64; cix++) {
        float xv0 = sX[p0 * 64 + cix];
        float xv1 = sX[(p0 + 1) * 64 + cix];
        ull x0 = pack2(xv0, xv0);
        ull x1 = pack2(xv1, xv1);
        const ulonglong2* mp = (const ulonglong2*)(sM + cix * 64 + og);
        ulonglong2 m0 = mp[0], m1 = mp[1];
        fma2(acc1[0][0], x0, m0.x); fma2(acc1[0][1], x0, m0.y);
        fma2(acc1[0][2], x0, m1.x); fma2(acc1[0][3], x0, m1.y);
        fma2(acc1[1][0], x1, m0.x); fma2(acc1[1][1], x1, m0.y);
        fma2(acc1[1][2], x1, m1.x); fma2(acc1[1][3], x1, m1.y);
    }
    float v1[2][8];
    float s1 = 0.f, q1 = 0.f;
    #pragma unroll
    for (int i = 0; i < 2; i++) {
        unpack2(acc1[i][0], v1[i][0], v1[i][1]); unpack2(acc1[i][1], v1[i][2], v1[i][3]);
        unpack2(acc1[i][2], v1[i][4], v1[i][5]); unpack2(acc1[i][3], v1[i][6], v1[i][7]);
        #pragma unroll
        for (int j = 0; j < 8; j++) { s1 += v1[i][j]; q1 += v1[i][j] * v1[i][j]; }
    }
    __syncthreads();
    blockReduce2_128(s1, q1, red);
    {
        float mean = s1 * (1.f / 2048.f);
        float var  = q1 * (1.f / 2048.f) - mean * mean;
        float rs   = rsqrtf(var + 1e-5f);
        #pragma unroll
        for (int i = 0; i < 2; i++)
            #pragma unroll
            for (int j = 0; j < 8; j++)
                sO1[(p0 + i) * 64 + og + j] = fmaxf((v1[i][j] - mean) * rs, 0.f);
    }
    __syncthreads();

    // ---- stage 2: out2[q][o] = sum_p S[q][p]*out1n[p][o] ----
    // thread owns rows ty*8..ty*8+7, cols tx*8..tx*8+7
    const int ty = t >> 3;                 // 0..15
    const int tx = t & 7;
    ull acc2[8][4];
    #pragma unroll
    for (int i = 0; i < 8; i++)
        #pragma unroll
        for (int j = 0; j < 4; j++) acc2[i][j] = 0ull;

    #pragma unroll 2
    for (int p = 0; p < 32; p++) {
        const float4* stp = (const float4*)(sST + p * 128 + ty * 8);
        float4 sv0 = stp[0], sv1 = stp[1];
        const ulonglong2* op = (const ulonglong2*)(sO1 + p * 64 + tx * 8);
        ulonglong2 b0 = op[0], b1 = op[1];
        float svv[8] = {sv0.x, sv0.y, sv0.z, sv0.w, sv1.x, sv1.y, sv1.z, sv1.w};
        #pragma unroll
        for (int i = 0; i < 8; i++) {
            ull sp = pack2(svv[i], svv[i]);
            fma2(acc2[i][0], sp, b0.x); fma2(acc2[i][1], sp, b0.y);
            fma2(acc2[i][2], sp, b1.x); fma2(acc2[i][3], sp, b1.y);
        }
    }
    float v2[8][8];
    float s2 = 0.f, q2 = 0.f;
    #pragma unroll
    for (int i = 0; i < 8; i++) {
        unpack2(acc2[i][0], v2[i][0], v2[i][1]); unpack2(acc2[i][1], v2[i][2], v2[i][3]);
        unpack2(acc2[i][2], v2[i][4], v2[i][5]); unpack2(acc2[i][3], v2[i][6], v2[i][7]);
        #pragma unroll
        for (int j = 0; j < 8; j++) { s2 += v2[i][j]; q2 += v2[i][j] * v2[i][j]; }
    }
    blockReduce2_128(s2, q2, red);
    float mean2 = s2 * (1.f / 8192.f);
    float var2  = q2 * (1.f / 8192.f) - mean2 * mean2;
    float rs2   = rsqrtf(var2 + 1e-5f);

    const size_t zbase = (size_t)(ng >> 2) * PCOLS + (size_t)(ng & 3) * TOTALP;
    #pragma unroll
    for (int i = 0; i < 8; i++) {
        const int qrow = ty * 8 + i;
        bf16 h[8], l[8];
        #pragma unroll
        for (int j = 0; j < 8; j++) {
            float o = fmaxf((v2[i][j] - mean2) * rs2, 0.f);
            f2hilo(o, h[j], l[j]);
        }
        size_t off = zbase + (size_t)qrow * 64 + tx * 8;
        *(uint4*)(Zhi + off) = make_uint4(bpk(h[0],h[1]), bpk(h[2],h[3]), bpk(h[4],h[5]), bpk(h[6],h[7]));
        *(uint4*)(Zlo + off) = make_uint4(bpk(l[0],l[1]), bpk(l[2],l[3]), bpk(l[4],l[5]), bpk(l[6],l[7]));
    }
}

// ---------------------------------------------------------------------------
__global__ void finalReduce(const float* __restrict__ part,
                            const float* __restrict__ query,
                            const float* __restrict__ bo,
                            float* __restrict__ out)
{
    int i = blockIdx.x * 256 + threadIdx.x;
    if (i >= NTOK * QDIM) return;
    float s = query[i] + bo[i & (QDIM - 1)];
    #pragma unroll
    for (int z = 0; z < SPLITK; z++)
        s += part[(size_t)z * NTOK * QDIM + i];
    out[i] = s;
}

// ---------------------------------------------------------------------------
extern "C" void kernel_launch(void* const* d_in, const int* in_sizes, int n_in,
                              void* d_out, int out_size)
{
    const float* x     = (const float*)d_in[0];
    const float* query = (const float*)d_in[1];
    const float* Wp    = (const float*)d_in[2];
    const float* bp    = (const float*)d_in[3];
    const float* Wo    = (const float*)d_in[4];
    const float* bo    = (const float*)d_in[5];
    float* out = (float*)d_out;

    float *pParams, *pPart;
    bf16 *pQh, *pQl, *pWpTh, *pWpTl, *pWoTh, *pWoTl, *pZh, *pZl;
    cudaGetSymbolAddress((void**)&pParams, g_params);
    cudaGetSymbolAddress((void**)&pPart, g_part);
    cudaGetSymbolAddress((void**)&pQh, g_qhi);
    cudaGetSymbolAddress((void**)&pQl, g_qlo);
    cudaGetSymbolAddress((void**)&pWpTh, g_wpT_hi);
    cudaGetSymbolAddress((void**)&pWpTl, g_wpT_lo);
    cudaGetSymbolAddress((void**)&pWoTh, g_woT_hi);
    cudaGetSymbolAddress((void**)&pWoTl, g_woT_lo);
    cudaGetSymbolAddress((void**)&pZh, g_zhi);
    cudaGetSymbolAddress((void**)&pZl, g_zlo);

    static cudaStream_t s1 = nullptr, s2 = nullptr;
    static cudaEvent_t evRoot = nullptr, evWp = nullptr, evWo = nullptr;
    if (!s1) {
        cudaStreamCreateWithFlags(&s1, cudaStreamNonBlocking);
        cudaStreamCreateWithFlags(&s2, cudaStreamNonBlocking);
        cudaEventCreateWithFlags(&evRoot, cudaEventDisableTiming);
        cudaEventCreateWithFlags(&evWp, cudaEventDisableTiming);
        cudaEventCreateWithFlags(&evWo, cudaEventDisableTiming);
        cudaFuncSetAttribute(gemm_mma, cudaFuncAttributeMaxDynamicSharedMemorySize, GSMEM);
    }

    // fork side streams from the main (capture) stream
    cudaEventRecord(evRoot, 0);
    cudaStreamWaitEvent(s1, evRoot, 0);
    cudaStreamWaitEvent(s2, evRoot, 0);

    // conversions: Q on main, WpT on s1 (needed by GEMM1), WoT on s2 (GEMM3)
    convQ<<<(NTOK * QDIM / 4 + 255) / 256, 256>>>(query, pQh, pQl);
    transConv<<<dim3(PCOLS / 32, QDIM / 32), dim3(32, 8), 0, s1>>>(Wp, pWpTh, pWpTl, QDIM, PCOLS);
    transConv<<<dim3(QDIM / 32, PCOLS / 32), dim3(32, 8), 0, s2>>>(Wo, pWoTh, pWoTl, PCOLS, QDIM);

    // join WpT before GEMM1 (WoT keeps running concurrently)
    cudaEventRecord(evWp, s1);
    cudaStreamWaitEvent(0, evWp, 0);

    // GEMM1: params[3600,32768] = q @ Wp + bp   (K=256 -> 8 chunks of 32)
    gemm_mma<<<dim3(PCOLS / 128, 29, 1), 256, GSMEM>>>(
        pQh, pQl, pWpTh, pWpTl, pParams, bp,
        NTOK, QDIM, QDIM, PCOLS, 8, 0);

    // fused middle -> Z (bf16 hi/lo)
    midkernel<<<NTOK * 4, 128>>>(x, pParams, pZh, pZl);

    // join WoT before GEMM3
    cudaEventRecord(evWo, s2);
    cudaStreamWaitEvent(0, evWo, 0);

    // GEMM3: part[z][3600,256] = Z[:, z*1024 : (z+1)*1024] @ Wo-chunk
    gemm_mma<<<dim3(QDIM / 128, 29, SPLITK), 256, GSMEM>>>(
        pZh, pZl, pWoTh, pWoTl, pPart, nullptr,
        NTOK, PCOLS, PCOLS, QDIM, (PCOLS / SPLITK) / 32, (int)((size_t)NTOK * QDIM));

    finalReduce<<<(NTOK * QDIM + 255) / 256, 256>>>(pPart, query, bo, out);
}

// round 7
// speedup vs baseline: 2.9957x; 1.0882x over previous
#include <cuda_runtime.h>
#include <cuda_bf16.h>
#include <cuda_fp16.h>
#include <cstdint>

// ---------------------------------------------------------------------------
// AdaptiveMixing on GB300 (compute_103 portable path):
//   params = query @ Wp + bp   [3600 x 32768]   fp16 2-pass mma.sync (err ~3e-4)
//   per (tok,grp): x@M -> LN -> relu -> S@ -> LN -> relu -> Z   (fp32 f32x2)
//   out = Z @ Wo + bo + query  [3600 x 256]     bf16 3-pass mma.sync (err ~1e-5)
// ---------------------------------------------------------------------------
#define NTOK   3600
#define QDIM   256
#define PCOLS  32768
#define TOTALP 8192
#define INP    32
#define EIN    64
#define SPLITK 32

typedef unsigned long long ull;
typedef __nv_bfloat16 bf16;
typedef __half fp16;

// ------------------------- device scratch (no allocs) ----------------------
__device__ float g_params[(size_t)NTOK * PCOLS];
__device__ fp16  g_qhi[(size_t)NTOK * QDIM];
__device__ fp16  g_qlo[(size_t)NTOK * QDIM];
__device__ fp16  g_wpT[(size_t)PCOLS * QDIM];               // WpT fp16 single
__device__ bf16  g_woT_hi[(size_t)QDIM * PCOLS];
__device__ bf16  g_woT_lo[(size_t)QDIM * PCOLS];
__device__ bf16  g_zhi[(size_t)NTOK * PCOLS];
__device__ bf16  g_zlo[(size_t)NTOK * PCOLS];
__device__ float g_part[(size_t)SPLITK * NTOK * QDIM];

// ----------------------------- helpers -------------------------------------
__device__ __forceinline__ ull pack2(float lo, float hi) {
    ull r; asm("mov.b64 %0, {%1,%2};" : "=l"(r) : "f"(lo), "f"(hi)); return r;
}
__device__ __forceinline__ void unpack2(ull v, float& lo, float& hi) {
    asm("mov.b64 {%0,%1}, %2;" : "=f"(lo), "=f"(hi) : "l"(v));
}
__device__ __forceinline__ void fma2(ull& d, ull a, ull b) {
    asm("fma.rn.f32x2 %0, %1, %2, %0;" : "+l"(d) : "l"(a), "l"(b));
}
__device__ __forceinline__ void f2hilo(float v, bf16& h, bf16& l) {
    h = __float2bfloat16(v);
    l = __float2bfloat16(v - __bfloat162float(h));
}
__device__ __forceinline__ void f2hiloH(float v, fp16& h, fp16& l) {
    h = __float2half_rn(v);
    l = __float2half_rn(v - __half2float(h));
}
__device__ __forceinline__ unsigned bpk(bf16 a, bf16 b) {
    return (unsigned)__bfloat16_as_ushort(a) | ((unsigned)__bfloat16_as_ushort(b) << 16);
}
__device__ __forceinline__ unsigned hpk(fp16 a, fp16 b) {
    return (unsigned)__half_as_ushort(a) | ((unsigned)__half_as_ushort(b) << 16);
}
__device__ __forceinline__ uint32_t smem_u32(const void* p) {
    uint32_t a;
    asm("{ .reg .u64 t; cvta.to.shared.u64 t, %1; cvt.u32.u64 %0, t; }" : "=r"(a) : "l"(p));
    return a;
}
__device__ __forceinline__ void ldsm4(uint32_t& r0, uint32_t& r1, uint32_t& r2, uint32_t& r3,
                                      uint32_t addr) {
    asm volatile("ldmatrix.sync.aligned.m8n8.x4.shared.b16 {%0,%1,%2,%3}, [%4];"
                 : "=r"(r0), "=r"(r1), "=r"(r2), "=r"(r3) : "r"(addr));
}
__device__ __forceinline__ void mma_bf16(float* c, const uint32_t* a, const uint32_t* b) {
    asm volatile(
        "mma.sync.aligned.m16n8k16.row.col.f32.bf16.bf16.f32 "
        "{%0,%1,%2,%3}, {%4,%5,%6,%7}, {%8,%9}, {%0,%1,%2,%3};"
        : "+f"(c[0]), "+f"(c[1]), "+f"(c[2]), "+f"(c[3])
        : "r"(a[0]), "r"(a[1]), "r"(a[2]), "r"(a[3]), "r"(b[0]), "r"(b[1]));
}
__device__ __forceinline__ void mma_f16(float* c, const uint32_t* a, const uint32_t* b) {
    asm volatile(
        "mma.sync.aligned.m16n8k16.row.col.f32.f16.f16.f32 "
        "{%0,%1,%2,%3}, {%4,%5,%6,%7}, {%8,%9}, {%0,%1,%2,%3};"
        : "+f"(c[0]), "+f"(c[1]), "+f"(c[2]), "+f"(c[3])
        : "r"(a[0]), "r"(a[1]), "r"(a[2]), "r"(a[3]), "r"(b[0]), "r"(b[1]));
}
__device__ __forceinline__ void cpa16(uint32_t dst, const void* src, int sz) {
    asm volatile("cp.async.cg.shared.global [%0], [%1], 16, %2;"
                 :: "r"(dst), "l"(src), "r"(sz) : "memory");
}
#define CP_COMMIT() asm volatile("cp.async.commit_group;" ::: "memory")
#define CP_WAIT(n)  asm volatile("cp.async.wait_group %0;" :: "n"(n) : "memory")

// ---------------------------------------------------------------------------
// Conversion kernels
// ---------------------------------------------------------------------------
__global__ void convQf16(const float* __restrict__ q, fp16* __restrict__ hi, fp16* __restrict__ lo) {
    int i = blockIdx.x * 256 + threadIdx.x;
    if (i >= NTOK * QDIM / 4) return;
    float4 v = ((const float4*)q)[i];
    fp16 h0,l0,h1,l1,h2,l2,h3,l3;
    f2hiloH(v.x,h0,l0); f2hiloH(v.y,h1,l1); f2hiloH(v.z,h2,l2); f2hiloH(v.w,h3,l3);
    ((uint2*)hi)[i] = make_uint2(hpk(h0,h1), hpk(h2,h3));
    ((uint2*)lo)[i] = make_uint2(hpk(l0,l1), hpk(l2,l3));
}

// transpose + convert to single fp16: in [R][C] f32 -> out[C][R]
__global__ void transConvF16(const float* __restrict__ in, fp16* __restrict__ o,
                             int R, int C) {
    __shared__ float tile[32][33];
    int c0 = blockIdx.x * 32, r0 = blockIdx.y * 32;
    int tx = threadIdx.x, ty = threadIdx.y;    // 32 x 8
    #pragma unroll
    for (int i = 0; i < 4; i++)
        tile[ty + 8 * i][tx] = in[(size_t)(r0 + ty + 8 * i) * C + c0 + tx];
    __syncthreads();
    #pragma unroll
    for (int i = 0; i < 4; i++) {
        float v = tile[tx][ty + 8 * i];
        o[(size_t)(c0 + ty + 8 * i) * R + r0 + tx] = __float2half_rn(v);
    }
}

// transpose + split: in [R][C] f32 -> out[C][R] bf16 hi/lo
__global__ void transConv(const float* __restrict__ in, bf16* __restrict__ oHi,
                          bf16* __restrict__ oLo, int R, int C) {
    __shared__ float tile[32][33];
    int c0 = blockIdx.x * 32, r0 = blockIdx.y * 32;
    int tx = threadIdx.x, ty = threadIdx.y;
    #pragma unroll
    for (int i = 0; i < 4; i++)
        tile[ty + 8 * i][tx] = in[(size_t)(r0 + ty + 8 * i) * C + c0 + tx];
    __syncthreads();
    #pragma unroll
    for (int i = 0; i < 4; i++) {
        float v = tile[tx][ty + 8 * i];
        bf16 h, l; f2hilo(v, h, l);
        size_t o = (size_t)(c0 + ty + 8 * i) * R + r0 + tx;
        oHi[o] = h; oLo[o] = l;
    }
}

// ---------------------------------------------------------------------------
// Common tiling constants
// ---------------------------------------------------------------------------
#define TILE_B   10240                   // 128 rows * 40 elem * 2B

// ======================= bf16 3-pass GEMM (GEMM3) ==========================
#define STAGE_B3 (4 * TILE_B)
#define GSMEM3   (2 * STAGE_B3)          // 81920

__global__ __launch_bounds__(256, 2)
void gemm_mma(const bf16* __restrict__ Ahi, const bf16* __restrict__ Alo,
              const bf16* __restrict__ Bhi, const bf16* __restrict__ Blo,
              float* __restrict__ C, const float* __restrict__ bias,
              int M, int lda, int ldb, int ldc, int nChunks, int partStride)
{
    extern __shared__ char smem[];
    const uint32_t sm0 = smem_u32(smem);
    const int t = threadIdx.x, lane = t & 31, w = t >> 5;
    const int wr = w & 3, wc = w >> 2;
    const int mrow0 = blockIdx.y * 128;
    const int n0 = blockIdx.x * 128;
    const int k0 = blockIdx.z * nChunks * 32;
    float* Cb = C + (size_t)blockIdx.z * partStride;

    const int row0_ = t >> 2, seg0 = t & 3;
    const int row1_ = (t + 256) >> 2, seg1 = (t + 256) & 3;
    const uint32_t so0 = (uint32_t)(row0_ * 40 + seg0 * 8) * 2;
    const uint32_t so1 = (uint32_t)(row1_ * 40 + seg1 * 8) * 2;
    const int okA0 = ((mrow0 + row0_) < M) ? 16 : 0;
    const int okA1 = ((mrow0 + row1_) < M) ? 16 : 0;
    const size_t gaBase0 = (size_t)(mrow0 + row0_) * lda + seg0 * 8;
    const size_t gaBase1 = (size_t)(mrow0 + row1_) * lda + seg1 * 8;
    const size_t gbBase0 = (size_t)(n0 + row0_) * ldb + seg0 * 8;
    const size_t gbBase1 = (size_t)(n0 + row1_) * ldb + seg1 * 8;

    const int q = lane >> 3, r8 = lane & 7;
    const uint32_t aoff = (uint32_t)((wr * 32 + r8 + ((q & 1) << 3)) * 40 + ((q >> 1) << 3)) * 2;
    const uint32_t boff = (uint32_t)((wc * 64 + r8 + ((q >> 1) << 3)) * 40 + ((q & 1) << 3)) * 2;

    float c[2][8][4];
    #pragma unroll
    for (int mt = 0; mt < 2; mt++)
        #pragma unroll
        for (int nt = 0; nt < 8; nt++)
            #pragma unroll
            for (int j = 0; j < 4; j++) c[mt][nt][j] = 0.f;

    auto stageLoad = [&](int stage, int kk) {
        uint32_t sb = sm0 + stage * STAGE_B3;
        cpa16(sb + 0 * TILE_B + so0, Ahi + gaBase0 + kk, okA0);
        cpa16(sb + 1 * TILE_B + so0, Alo + gaBase0 + kk, okA0);
        cpa16(sb + 2 * TILE_B + so0, Bhi + gbBase0 + kk, 16);
        cpa16(sb + 3 * TILE_B + so0, Blo + gbBase0 + kk, 16);
        cpa16(sb + 0 * TILE_B + so1, Ahi + gaBase1 + kk, okA1);
        cpa16(sb + 1 * TILE_B + so1, Alo + gaBase1 + kk, okA1);
        cpa16(sb + 2 * TILE_B + so1, Bhi + gbBase1 + kk, 16);
        cpa16(sb + 3 * TILE_B + so1, Blo + gbBase1 + kk, 16);
        CP_COMMIT();
    };

    stageLoad(0, k0);

    for (int ch = 0; ch < nChunks; ch++) {
        const int st = ch & 1;
        const bool more = (ch + 1) < nChunks;
        if (more) stageLoad(st ^ 1, k0 + (ch + 1) * 32);
        if (more) { CP_WAIT(1); } else { CP_WAIT(0); }
        __syncthreads();

        const uint32_t base = sm0 + st * STAGE_B3;
        #pragma unroll
        for (int ks = 0; ks < 2; ks++) {
            uint32_t ah[2][4], al2[2][4];
            #pragma unroll
            for (int mt = 0; mt < 2; mt++) {
                uint32_t aA = base + aoff + mt * (16 * 80) + ks * 32;
                ldsm4(ah[mt][0], ah[mt][1], ah[mt][2], ah[mt][3], aA);
                ldsm4(al2[mt][0], al2[mt][1], al2[mt][2], al2[mt][3], aA + TILE_B);
            }
            #pragma unroll
            for (int g = 0; g < 4; g++) {
                uint32_t bh[4], bl[4];
                uint32_t aB = base + 2 * TILE_B + boff + g * (16 * 80) + ks * 32;
                ldsm4(bh[0], bh[1], bh[2], bh[3], aB);
                ldsm4(bl[0], bl[1], bl[2], bl[3], aB + TILE_B);
                #pragma unroll
                for (int mt = 0; mt < 2; mt++) {
                    mma_bf16(c[mt][2*g],   ah[mt],  &bh[0]);
                    mma_bf16(c[mt][2*g+1], ah[mt],  &bh[2]);
                    mma_bf16(c[mt][2*g],   ah[mt],  &bl[0]);
                    mma_bf16(c[mt][2*g+1], ah[mt],  &bl[2]);
                    mma_bf16(c[mt][2*g],   al2[mt], &bh[0]);
                    mma_bf16(c[mt][2*g+1], al2[mt], &bh[2]);
                }
            }
        }
        __syncthreads();
    }

    const int crow = mrow0 + wr * 32 + (lane >> 2);
    const int ccol = n0 + wc * 64 + (lane & 3) * 2;
    #pragma unroll
    for (int mt = 0; mt < 2; mt++) {
        #pragma unroll
        for (int nt = 0; nt < 8; nt++) {
            int col = ccol + nt * 8;
            float b0 = 0.f, b1 = 0.f;
            if (bias) { b0 = bias[col]; b1 = bias[col + 1]; }
            int r0 = crow + mt * 16;
            if (r0 < M) {
                float2 v = make_float2(c[mt][nt][0] + b0, c[mt][nt][1] + b1);
                *(float2*)(Cb + (size_t)r0 * ldc + col) = v;
            }
            int r1 = r0 + 8;
            if (r1 < M) {
                float2 v = make_float2(c[mt][nt][2] + b0, c[mt][nt][3] + b1);
                *(float2*)(Cb + (size_t)r1 * ldc + col) = v;
            }
        }
    }
}

// ======================= fp16 2-pass GEMM (GEMM1) ==========================
// A split hi/lo fp16, B single fp16. C = Ah*B + Al*B.
#define STAGE_B2 (3 * TILE_B)
#define GSMEM2   (2 * STAGE_B2)          // 61440

__global__ __launch_bounds__(256, 2)
void gemm_mma2(const fp16* __restrict__ Ahi, const fp16* __restrict__ Alo,
               const fp16* __restrict__ B,
               float* __restrict__ C, const float* __restrict__ bias,
               int M, int lda, int ldb, int ldc, int nChunks)
{
    extern __shared__ char smem[];
    const uint32_t sm0 = smem_u32(smem);
    const int t = threadIdx.x, lane = t & 31, w = t >> 5;
    const int wr = w & 3, wc = w >> 2;
    const int mrow0 = blockIdx.y * 128;
    const int n0 = blockIdx.x * 128;

    const int row0_ = t >> 2, seg0 = t & 3;
    const int row1_ = (t + 256) >> 2, seg1 = (t + 256) & 3;
    const uint32_t so0 = (uint32_t)(row0_ * 40 + seg0 * 8) * 2;
    const uint32_t so1 = (uint32_t)(row1_ * 40 + seg1 * 8) * 2;
    const int okA0 = ((mrow0 + row0_) < M) ? 16 : 0;
    const int okA1 = ((mrow0 + row1_) < M) ? 16 : 0;
    const size_t gaBase0 = (size_t)(mrow0 + row0_) * lda + seg0 * 8;
    const size_t gaBase1 = (size_t)(mrow0 + row1_) * lda + seg1 * 8;
    const size_t gbBase0 = (size_t)(n0 + row0_) * ldb + seg0 * 8;
    const size_t gbBase1 = (size_t)(n0 + row1_) * ldb + seg1 * 8;

    const int q = lane >> 3, r8 = lane & 7;
    const uint32_t aoff = (uint32_t)((wr * 32 + r8 + ((q & 1) << 3)) * 40 + ((q >> 1) << 3)) * 2;
    const uint32_t boff = (uint32_t)((wc * 64 + r8 + ((q >> 1) << 3)) * 40 + ((q & 1) << 3)) * 2;

    float c[2][8][4];
    #pragma unroll
    for (int mt = 0; mt < 2; mt++)
        #pragma unroll
        for (int nt = 0; nt < 8; nt++)
            #pragma unroll
            for (int j = 0; j < 4; j++) c[mt][nt][j] = 0.f;

    auto stageLoad = [&](int stage, int kk) {
        uint32_t sb = sm0 + stage * STAGE_B2;
        cpa16(sb + 0 * TILE_B + so0, Ahi + gaBase0 + kk, okA0);
        cpa16(sb + 1 * TILE_B + so0, Alo + gaBase0 + kk, okA0);
        cpa16(sb + 2 * TILE_B + so0, B   + gbBase0 + kk, 16);
        cpa16(sb + 0 * TILE_B + so1, Ahi + gaBase1 + kk, okA1);
        cpa16(sb + 1 * TILE_B + so1, Alo + gaBase1 + kk, okA1);
        cpa16(sb + 2 * TILE_B + so1, B   + gbBase1 + kk, 16);
        CP_COMMIT();
    };

    stageLoad(0, 0);

    for (int ch = 0; ch < nChunks; ch++) {
        const int st = ch & 1;
        const bool more = (ch + 1) < nChunks;
        if (more) stageLoad(st ^ 1, (ch + 1) * 32);
        if (more) { CP_WAIT(1); } else { CP_WAIT(0); }
        __syncthreads();

        const uint32_t base = sm0 + st * STAGE_B2;
        #pragma unroll
        for (int ks = 0; ks < 2; ks++) {
            uint32_t ah[2][4], al2[2][4];
            #pragma unroll
            for (int mt = 0; mt < 2; mt++) {
                uint32_t aA = base + aoff + mt * (16 * 80) + ks * 32;
                ldsm4(ah[mt][0], ah[mt][1], ah[mt][2], ah[mt][3], aA);
                ldsm4(al2[mt][0], al2[mt][1], al2[mt][2], al2[mt][3], aA + TILE_B);
            }
            #pragma unroll
            for (int g = 0; g < 4; g++) {
                uint32_t bh[4];
                uint32_t aB = base + 2 * TILE_B + boff + g * (16 * 80) + ks * 32;
                ldsm4(bh[0], bh[1], bh[2], bh[3], aB);
                #pragma unroll
                for (int mt = 0; mt < 2; mt++) {
                    mma_f16(c[mt][2*g],   ah[mt],  &bh[0]);
                    mma_f16(c[mt][2*g+1], ah[mt],  &bh[2]);
                    mma_f16(c[mt][2*g],   al2[mt], &bh[0]);
                    mma_f16(c[mt][2*g+1], al2[mt], &bh[2]);
                }
            }
        }
        __syncthreads();
    }

    const int crow = mrow0 + wr * 32 + (lane >> 2);
    const int ccol = n0 + wc * 64 + (lane & 3) * 2;
    #pragma unroll
    for (int mt = 0; mt < 2; mt++) {
        #pragma unroll
        for (int nt = 0; nt < 8; nt++) {
            int col = ccol + nt * 8;
            float b0 = bias[col], b1 = bias[col + 1];
            int r0 = crow + mt * 16;
            if (r0 < M) {
                float2 v = make_float2(c[mt][nt][0] + b0, c[mt][nt][1] + b1);
                *(float2*)(C + (size_t)r0 * ldc + col) = v;
            }
            int r1 = r0 + 8;
            if (r1 < M) {
                float2 v = make_float2(c[mt][nt][2] + b0, c[mt][nt][3] + b1);
                *(float2*)(C + (size_t)r1 * ldc + col) = v;
            }
        }
    }
}

// ---------------------------------------------------------------------------
// Block reduction of (sum, sumsq) over 128 threads / 4 warps.
// ---------------------------------------------------------------------------
__device__ __forceinline__ void blockReduce2_128(float& s, float& q, float* red) {
    #pragma unroll
    for (int o = 16; o > 0; o >>= 1) {
        s += __shfl_xor_sync(0xffffffffu, s, o);
        q += __shfl_xor_sync(0xffffffffu, q, o);
    }
    const int t = threadIdx.x;
    if ((t & 31) == 0) { red[t >> 5] = s; red[4 + (t >> 5)] = q; }
    __syncthreads();
    s = red[0] + red[1] + red[2] + red[3];
    q = red[4] + red[5] + red[6] + red[7];
    __syncthreads();
}

// ---------------------------------------------------------------------------
// Fused middle v3 (same as R6)
// ---------------------------------------------------------------------------
__global__ __launch_bounds__(128)
void midkernel(const float* __restrict__ x, const float* __restrict__ params,
               bf16* __restrict__ Zhi, bf16* __restrict__ Zlo)
{
    __shared__ float smem[12288];
    float* sX  = smem;
    float* sM  = smem + 2048;
    float* sST = smem + 6144;
    float* sO1 = smem + 10240;
    float* red = smem;

    const int ng = blockIdx.x;
    const int t  = threadIdx.x;
    const float* xb = x + (size_t)ng * (INP * EIN);
    const float* pb = params + (size_t)(ng >> 2) * PCOLS + (size_t)(ng & 3) * TOTALP;

    {
        const float4* x4 = (const float4*)xb;
        const float4* m4 = (const float4*)pb;
        const float4* s4 = (const float4*)(pb + 4096);
        ((float4*)sX)[t]       = x4[t];
        ((float4*)sX)[t + 128] = x4[t + 128];
        ((float4*)sX)[t + 256] = x4[t + 256];
        ((float4*)sX)[t + 384] = x4[t + 384];
        #pragma unroll
        for (int i = 0; i < 8; i++)
            ((float4*)sM)[t + 128 * i] = m4[t + 128 * i];
        #pragma unroll
        for (int i = 0; i < 8; i++) {
            int idx = t + 128 * i;
            float4 v = s4[idx];
            int qq = idx >> 3;
            int p4 = (idx & 7) << 2;
            sST[(p4 + 0) * 128 + qq] = v.x;
            sST[(p4 + 1) * 128 + qq] = v.y;
            sST[(p4 + 2) * 128 + qq] = v.z;
            sST[(p4 + 3) * 128 + qq] = v.w;
        }
    }
    __syncthreads();

    const int p0 = (t >> 3) << 1;
    const int og = (t & 7) << 3;
    ull acc1[2][4];
    #pragma unroll
    for (int i = 0; i < 2; i++)
        #pragma unroll
        for (int j = 0; j < 4; j++) acc1[i][j] = 0ull;

    #pragma unroll 4
    for (int cix = 0; cix < 64; cix++) {
        float xv0 = sX[p0 * 64 + cix];
        float xv1 = sX[(p0 + 1) * 64 + cix];
        ull x0 = pack2(xv0, xv0);
        ull x1 = pack2(xv1, xv1);
        const ulonglong2* mp = (const ulonglong2*)(sM + cix * 64 + og);
        ulonglong2 m0 = mp[0], m1 = mp[1];
        fma2(acc1[0][0], x0, m0.x); fma2(acc1[0][1], x0, m0.y);
        fma2(acc1[0][2], x0, m1.x); fma2(acc1[0][3], x0, m1.y);
        fma2(acc1[1][0], x1, m0.x); fma2(acc1[1][1], x1, m0.y);
        fma2(acc1[1][2], x1, m1.x); fma2(acc1[1][3], x1, m1.y);
    }
    float v1[2][8];
    float s1 = 0.f, q1 = 0.f;
    #pragma unroll
    for (int i = 0; i < 2; i++) {
        unpack2(acc1[i][0], v1[i][0], v1[i][1]); unpack2(acc1[i][1], v1[i][2], v1[i][3]);
        unpack2(acc1[i][2], v1[i][4], v1[i][5]); unpack2(acc1[i][3], v1[i][6], v1[i][7]);
        #pragma unroll
        for (int j = 0; j < 8; j++) { s1 += v1[i][j]; q1 += v1[i][j] * v1[i][j]; }
    }
    __syncthreads();
    blockReduce2_128(s1, q1, red);
    {
        float mean = s1 * (1.f / 2048.f);
        float var  = q1 * (1.f / 2048.f) - mean * mean;
        float rs   = rsqrtf(var + 1e-5f);
        #pragma unroll
        for (int i = 0; i < 2; i++)
            #pragma unroll
            for (int j = 0; j < 8; j++)
                sO1[(p0 + i) * 64 + og + j] = fmaxf((v1[i][j] - mean) * rs, 0.f);
    }
    __syncthreads();

    const int ty = t >> 3;
    const int tx = t & 7;
    ull acc2[8][4];
    #pragma unroll
    for (int i = 0; i < 8; i++)
        #pragma unroll
        for (int j = 0; j < 4; j++) acc2[i][j] = 0ull;

    #pragma unroll 2
    for (int p = 0; p < 32; p++) {
        const float4* stp = (const float4*)(sST + p * 128 + ty * 8);
        float4 sv0 = stp[0], sv1 = stp[1];
        const ulonglong2* op = (const ulonglong2*)(sO1 + p * 64 + tx * 8);
        ulonglong2 b0 = op[0], b1 = op[1];
        float svv[8] = {sv0.x, sv0.y, sv0.z, sv0.w, sv1.x, sv1.y, sv1.z, sv1.w};
        #pragma unroll
        for (int i = 0; i < 8; i++) {
            ull sp = pack2(svv[i], svv[i]);
            fma2(acc2[i][0], sp, b0.x); fma2(acc2[i][1], sp, b0.y);
            fma2(acc2[i][2], sp, b1.x); fma2(acc2[i][3], sp, b1.y);
        }
    }
    float v2[8][8];
    float s2 = 0.f, q2 = 0.f;
    #pragma unroll
    for (int i = 0; i < 8; i++) {
        unpack2(acc2[i][0], v2[i][0], v2[i][1]); unpack2(acc2[i][1], v2[i][2], v2[i][3]);
        unpack2(acc2[i][2], v2[i][4], v2[i][5]); unpack2(acc2[i][3], v2[i][6], v2[i][7]);
        #pragma unroll
        for (int j = 0; j < 8; j++) { s2 += v2[i][j]; q2 += v2[i][j] * v2[i][j]; }
    }
    blockReduce2_128(s2, q2, red);
    float mean2 = s2 * (1.f / 8192.f);
    float var2  = q2 * (1.f / 8192.f) - mean2 * mean2;
    float rs2   = rsqrtf(var2 + 1e-5f);

    const size_t zbase = (size_t)(ng >> 2) * PCOLS + (size_t)(ng & 3) * TOTALP;
    #pragma unroll
    for (int i = 0; i < 8; i++) {
        const int qrow = ty * 8 + i;
        bf16 h[8], l[8];
        #pragma unroll
        for (int j = 0; j < 8; j++) {
            float o = fmaxf((v2[i][j] - mean2) * rs2, 0.f);
            f2hilo(o, h[j], l[j]);
        }
        size_t off = zbase + (size_t)qrow * 64 + tx * 8;
        *(uint4*)(Zhi + off) = make_uint4(bpk(h[0],h[1]), bpk(h[2],h[3]), bpk(h[4],h[5]), bpk(h[6],h[7]));
        *(uint4*)(Zlo + off) = make_uint4(bpk(l[0],l[1]), bpk(l[2],l[3]), bpk(l[4],l[5]), bpk(l[6],l[7]));
    }
}

// ---------------------------------------------------------------------------
__global__ void finalReduce(const float* __restrict__ part,
                            const float* __restrict__ query,
                            const float* __restrict__ bo,
                            float* __restrict__ out)
{
    int i = blockIdx.x * 256 + threadIdx.x;
    if (i >= NTOK * QDIM) return;
    float s = query[i] + bo[i & (QDIM - 1)];
    #pragma unroll
    for (int z = 0; z < SPLITK; z++)
        s += part[(size_t)z * NTOK * QDIM + i];
    out[i] = s;
}

// ---------------------------------------------------------------------------
extern "C" void kernel_launch(void* const* d_in, const int* in_sizes, int n_in,
                              void* d_out, int out_size)
{
    const float* x     = (const float*)d_in[0];
    const float* query = (const float*)d_in[1];
    const float* Wp    = (const float*)d_in[2];
    const float* bp    = (const float*)d_in[3];
    const float* Wo    = (const float*)d_in[4];
    const float* bo    = (const float*)d_in[5];
    float* out = (float*)d_out;

    float *pParams, *pPart;
    fp16 *pQh, *pQl, *pWpT;
    bf16 *pWoTh, *pWoTl, *pZh, *pZl;
    cudaGetSymbolAddress((void**)&pParams, g_params);
    cudaGetSymbolAddress((void**)&pPart, g_part);
    cudaGetSymbolAddress((void**)&pQh, g_qhi);
    cudaGetSymbolAddress((void**)&pQl, g_qlo);
    cudaGetSymbolAddress((void**)&pWpT, g_wpT);
    cudaGetSymbolAddress((void**)&pWoTh, g_woT_hi);
    cudaGetSymbolAddress((void**)&pWoTl, g_woT_lo);
    cudaGetSymbolAddress((void**)&pZh, g_zhi);
    cudaGetSymbolAddress((void**)&pZl, g_zlo);

    static cudaStream_t s1 = nullptr, s2 = nullptr;
    static cudaEvent_t evRoot = nullptr, evWp = nullptr, evWo = nullptr;
    if (!s1) {
        cudaStreamCreateWithFlags(&s1, cudaStreamNonBlocking);
        cudaStreamCreateWithFlags(&s2, cudaStreamNonBlocking);
        cudaEventCreateWithFlags(&evRoot, cudaEventDisableTiming);
        cudaEventCreateWithFlags(&evWp, cudaEventDisableTiming);
        cudaEventCreateWithFlags(&evWo, cudaEventDisableTiming);
        cudaFuncSetAttribute(gemm_mma, cudaFuncAttributeMaxDynamicSharedMemorySize, GSMEM3);
        cudaFuncSetAttribute(gemm_mma2, cudaFuncAttributeMaxDynamicSharedMemorySize, GSMEM2);
    }

    cudaEventRecord(evRoot, 0);
    cudaStreamWaitEvent(s1, evRoot, 0);
    cudaStreamWaitEvent(s2, evRoot, 0);

    convQf16<<<(NTOK * QDIM / 4 + 255) / 256, 256>>>(query, pQh, pQl);
    transConvF16<<<dim3(PCOLS / 32, QDIM / 32), dim3(32, 8), 0, s1>>>(Wp, pWpT, QDIM, PCOLS);
    transConv<<<dim3(QDIM / 32, PCOLS / 32), dim3(32, 8), 0, s2>>>(Wo, pWoTh, pWoTl, PCOLS, QDIM);

    cudaEventRecord(evWp, s1);
    cudaStreamWaitEvent(0, evWp, 0);

    // GEMM1: params = q @ Wp + bp   (fp16 2-pass, K=256 -> 8 chunks of 32)
    gemm_mma2<<<dim3(PCOLS / 128, 29, 1), 256, GSMEM2>>>(
        pQh, pQl, pWpT, pParams, bp, NTOK, QDIM, QDIM, PCOLS, 8);

    midkernel<<<NTOK * 4, 128>>>(x, pParams, pZh, pZl);

    cudaEventRecord(evWo, s2);
    cudaStreamWaitEvent(0, evWo, 0);

    // GEMM3: part[z] = Z[:, z*1024:(z+1)*1024] @ Wo-chunk   (bf16 3-pass)
    gemm_mma<<<dim3(QDIM / 128, 29, SPLITK), 256, GSMEM3>>>(
        pZh, pZl, pWoTh, pWoTl, pPart, nullptr,
        NTOK, PCOLS, PCOLS, QDIM, (PCOLS / SPLITK) / 32, (int)((size_t)NTOK * QDIM));

    finalReduce<<<(NTOK * QDIM + 255) / 256, 256>>>(pPart, query, bo, out);
}

// round 8
// speedup vs baseline: 3.3255x; 1.1101x over previous
#include <cuda_runtime.h>
#include <cuda_bf16.h>
#include <cuda_fp16.h>
#include <cstdint>

// ---------------------------------------------------------------------------
// AdaptiveMixing on GB300 (compute_103 portable path):
//   params = query @ Wp + bp   [3600 x 32768]   fp16 2-pass mma.sync
//   per (tok,grp): x@M -> LN -> relu -> S@ -> LN -> relu -> Z   (fp32 f32x2)
//   out = Z @ Wo + bo + query  [3600 x 256]     fp16 2-pass mma.sync
// A split hi/lo fp16 (A error negligible), B single fp16 (~2.8e-4 per GEMM).
// Total rel err ~4e-4, gate is 1e-3.
// ---------------------------------------------------------------------------
#define NTOK   3600
#define QDIM   256
#define PCOLS  32768
#define TOTALP 8192
#define INP    32
#define EIN    64
#define SPLITK 32

typedef unsigned long long ull;
typedef __half fp16;

// ------------------------- device scratch (no allocs) ----------------------
__device__ float g_params[(size_t)NTOK * PCOLS];
__device__ fp16  g_qhi[(size_t)NTOK * QDIM];
__device__ fp16  g_qlo[(size_t)NTOK * QDIM];
__device__ fp16  g_wpT[(size_t)PCOLS * QDIM];
__device__ fp16  g_woT[(size_t)QDIM * PCOLS];
__device__ fp16  g_zhi[(size_t)NTOK * PCOLS];
__device__ fp16  g_zlo[(size_t)NTOK * PCOLS];
__device__ float g_part[(size_t)SPLITK * NTOK * QDIM];

// ----------------------------- helpers -------------------------------------
__device__ __forceinline__ ull pack2(float lo, float hi) {
    ull r; asm("mov.b64 %0, {%1,%2};" : "=l"(r) : "f"(lo), "f"(hi)); return r;
}
__device__ __forceinline__ void unpack2(ull v, float& lo, float& hi) {
    asm("mov.b64 {%0,%1}, %2;" : "=f"(lo), "=f"(hi) : "l"(v));
}
__device__ __forceinline__ void fma2(ull& d, ull a, ull b) {
    asm("fma.rn.f32x2 %0, %1, %2, %0;" : "+l"(d) : "l"(a), "l"(b));
}
__device__ __forceinline__ void f2hiloH(float v, fp16& h, fp16& l) {
    h = __float2half_rn(v);
    l = __float2half_rn(v - __half2float(h));
}
__device__ __forceinline__ unsigned hpk(fp16 a, fp16 b) {
    return (unsigned)__half_as_ushort(a) | ((unsigned)__half_as_ushort(b) << 16);
}
__device__ __forceinline__ uint32_t smem_u32(const void* p) {
    uint32_t a;
    asm("{ .reg .u64 t; cvta.to.shared.u64 t, %1; cvt.u32.u64 %0, t; }" : "=r"(a) : "l"(p));
    return a;
}
__device__ __forceinline__ void ldsm4(uint32_t& r0, uint32_t& r1, uint32_t& r2, uint32_t& r3,
                                      uint32_t addr) {
    asm volatile("ldmatrix.sync.aligned.m8n8.x4.shared.b16 {%0,%1,%2,%3}, [%4];"
                 : "=r"(r0), "=r"(r1), "=r"(r2), "=r"(r3) : "r"(addr));
}
__device__ __forceinline__ void mma_f16(float* c, const uint32_t* a, const uint32_t* b) {
    asm volatile(
        "mma.sync.aligned.m16n8k16.row.col.f32.f16.f16.f32 "
        "{%0,%1,%2,%3}, {%4,%5,%6,%7}, {%8,%9}, {%0,%1,%2,%3};"
        : "+f"(c[0]), "+f"(c[1]), "+f"(c[2]), "+f"(c[3])
        : "r"(a[0]), "r"(a[1]), "r"(a[2]), "r"(a[3]), "r"(b[0]), "r"(b[1]));
}
__device__ __forceinline__ void cpa16(uint32_t dst, const void* src, int sz) {
    asm volatile("cp.async.cg.shared.global [%0], [%1], 16, %2;"
                 :: "r"(dst), "l"(src), "r"(sz) : "memory");
}
#define CP_COMMIT() asm volatile("cp.async.commit_group;" ::: "memory")
#define CP_WAIT(n)  asm volatile("cp.async.wait_group %0;" :: "n"(n) : "memory")

// ---------------------------------------------------------------------------
// Conversion kernels
// ---------------------------------------------------------------------------
__global__ void convQf16(const float* __restrict__ q, fp16* __restrict__ hi, fp16* __restrict__ lo) {
    int i = blockIdx.x * 256 + threadIdx.x;
    if (i >= NTOK * QDIM / 4) return;
    float4 v = ((const float4*)q)[i];
    fp16 h0,l0,h1,l1,h2,l2,h3,l3;
    f2hiloH(v.x,h0,l0); f2hiloH(v.y,h1,l1); f2hiloH(v.z,h2,l2); f2hiloH(v.w,h3,l3);
    ((uint2*)hi)[i] = make_uint2(hpk(h0,h1), hpk(h2,h3));
    ((uint2*)lo)[i] = make_uint2(hpk(l0,l1), hpk(l2,l3));
}

// transpose + convert to single fp16: in [R][C] f32 -> out[C][R]
__global__ void transConvF16(const float* __restrict__ in, fp16* __restrict__ o,
                             int R, int C) {
    __shared__ float tile[32][33];
    int c0 = blockIdx.x * 32, r0 = blockIdx.y * 32;
    int tx = threadIdx.x, ty = threadIdx.y;    // 32 x 8
    #pragma unroll
    for (int i = 0; i < 4; i++)
        tile[ty + 8 * i][tx] = in[(size_t)(r0 + ty + 8 * i) * C + c0 + tx];
    __syncthreads();
    #pragma unroll
    for (int i = 0; i < 4; i++) {
        float v = tile[tx][ty + 8 * i];
        o[(size_t)(c0 + ty + 8 * i) * R + r0 + tx] = __float2half_rn(v);
    }
}

// ---------------------------------------------------------------------------
// fp16 2-pass GEMM: C = (Ah + Al) * B^T, A split hi/lo, B single.
// 128x128 CTA tile, BK=32, 8 warps (4x2), warp tile 32x64.
// smem row pitch 40 halves (80B) -> conflict-free ldmatrix. cp.async 2-stage.
// ---------------------------------------------------------------------------
#define TILE_B   10240                   // 128 rows * 40 * 2B
#define STAGE_B2 (3 * TILE_B)            // Ah, Al, B
#define GSMEM2   (2 * STAGE_B2)          // 61440

__global__ __launch_bounds__(256, 2)
void gemm_mma2(const fp16* __restrict__ Ahi, const fp16* __restrict__ Alo,
               const fp16* __restrict__ B,
               float* __restrict__ C, const float* __restrict__ bias,
               int M, int lda, int ldb, int ldc, int nChunks, int partStride)
{
    extern __shared__ char smem[];
    const uint32_t sm0 = smem_u32(smem);
    const int t = threadIdx.x, lane = t & 31, w = t >> 5;
    const int wr = w & 3, wc = w >> 2;
    const int mrow0 = blockIdx.y * 128;
    const int n0 = blockIdx.x * 128;
    const int k0 = blockIdx.z * nChunks * 32;
    float* Cb = C + (size_t)blockIdx.z * partStride;

    const int row0_ = t >> 2, seg0 = t & 3;
    const int row1_ = (t + 256) >> 2, seg1 = (t + 256) & 3;
    const uint32_t so0 = (uint32_t)(row0_ * 40 + seg0 * 8) * 2;
    const uint32_t so1 = (uint32_t)(row1_ * 40 + seg1 * 8) * 2;
    const int okA0 = ((mrow0 + row0_) < M) ? 16 : 0;
    const int okA1 = ((mrow0 + row1_) < M) ? 16 : 0;
    const size_t gaBase0 = (size_t)(mrow0 + row0_) * lda + seg0 * 8 + k0;
    const size_t gaBase1 = (size_t)(mrow0 + row1_) * lda + seg1 * 8 + k0;
    const size_t gbBase0 = (size_t)(n0 + row0_) * ldb + seg0 * 8 + k0;
    const size_t gbBase1 = (size_t)(n0 + row1_) * ldb + seg1 * 8 + k0;

    const int q = lane >> 3, r8 = lane & 7;
    const uint32_t aoff = (uint32_t)((wr * 32 + r8 + ((q & 1) << 3)) * 40 + ((q >> 1) << 3)) * 2;
    const uint32_t boff = (uint32_t)((wc * 64 + r8 + ((q >> 1) << 3)) * 40 + ((q & 1) << 3)) * 2;

    float c[2][8][4];
    #pragma unroll
    for (int mt = 0; mt < 2; mt++)
        #pragma unroll
        for (int nt = 0; nt < 8; nt++)
            #pragma unroll
            for (int j = 0; j < 4; j++) c[mt][nt][j] = 0.f;

    auto stageLoad = [&](int stage, int kk) {
        uint32_t sb = sm0 + stage * STAGE_B2;
        cpa16(sb + 0 * TILE_B + so0, Ahi + gaBase0 + kk, okA0);
        cpa16(sb + 1 * TILE_B + so0, Alo + gaBase0 + kk, okA0);
        cpa16(sb + 2 * TILE_B + so0, B   + gbBase0 + kk, 16);
        cpa16(sb + 0 * TILE_B + so1, Ahi + gaBase1 + kk, okA1);
        cpa16(sb + 1 * TILE_B + so1, Alo + gaBase1 + kk, okA1);
        cpa16(sb + 2 * TILE_B + so1, B   + gbBase1 + kk, 16);
        CP_COMMIT();
    };

    stageLoad(0, 0);

    for (int ch = 0; ch < nChunks; ch++) {
        const int st = ch & 1;
        const bool more = (ch + 1) < nChunks;
        if (more) stageLoad(st ^ 1, (ch + 1) * 32);
        if (more) { CP_WAIT(1); } else { CP_WAIT(0); }
        __syncthreads();

        const uint32_t base = sm0 + st * STAGE_B2;
        #pragma unroll
        for (int ks = 0; ks < 2; ks++) {
            uint32_t ah[2][4], al2[2][4];
            #pragma unroll
            for (int mt = 0; mt < 2; mt++) {
                uint32_t aA = base + aoff + mt * (16 * 80) + ks * 32;
                ldsm4(ah[mt][0], ah[mt][1], ah[mt][2], ah[mt][3], aA);
                ldsm4(al2[mt][0], al2[mt][1], al2[mt][2], al2[mt][3], aA + TILE_B);
            }
            #pragma unroll
            for (int g = 0; g < 4; g++) {
                uint32_t bh[4];
                uint32_t aB = base + 2 * TILE_B + boff + g * (16 * 80) + ks * 32;
                ldsm4(bh[0], bh[1], bh[2], bh[3], aB);
                #pragma unroll
                for (int mt = 0; mt < 2; mt++) {
                    mma_f16(c[mt][2*g],   ah[mt],  &bh[0]);
                    mma_f16(c[mt][2*g+1], ah[mt],  &bh[2]);
                    mma_f16(c[mt][2*g],   al2[mt], &bh[0]);
                    mma_f16(c[mt][2*g+1], al2[mt], &bh[2]);
                }
            }
        }
        __syncthreads();
    }

    const int crow = mrow0 + wr * 32 + (lane >> 2);
    const int ccol = n0 + wc * 64 + (lane & 3) * 2;
    #pragma unroll
    for (int mt = 0; mt < 2; mt++) {
        #pragma unroll
        for (int nt = 0; nt < 8; nt++) {
            int col = ccol + nt * 8;
            float b0 = 0.f, b1 = 0.f;
            if (bias) { b0 = bias[col]; b1 = bias[col + 1]; }
            int r0 = crow + mt * 16;
            if (r0 < M) {
                float2 v = make_float2(c[mt][nt][0] + b0, c[mt][nt][1] + b1);
                *(float2*)(Cb + (size_t)r0 * ldc + col) = v;
            }
            int r1 = r0 + 8;
            if (r1 < M) {
                float2 v = make_float2(c[mt][nt][2] + b0, c[mt][nt][3] + b1);
                *(float2*)(Cb + (size_t)r1 * ldc + col) = v;
            }
        }
    }
}

// ---------------------------------------------------------------------------
// Block reduction of (sum, sumsq) over 128 threads / 4 warps.
// ---------------------------------------------------------------------------
__device__ __forceinline__ void blockReduce2_128(float& s, float& q, float* red) {
    #pragma unroll
    for (int o = 16; o > 0; o >>= 1) {
        s += __shfl_xor_sync(0xffffffffu, s, o);
        q += __shfl_xor_sync(0xffffffffu, q, o);
    }
    const int t = threadIdx.x;
    if ((t & 31) == 0) { red[t >> 5] = s; red[4 + (t >> 5)] = q; }
    __syncthreads();
    s = red[0] + red[1] + red[2] + red[3];
    q = red[4] + red[5] + red[6] + red[7];
    __syncthreads();
}

// ---------------------------------------------------------------------------
// Fused middle: 128 threads/CTA; outputs Z as fp16 hi/lo
// ---------------------------------------------------------------------------
__global__ __launch_bounds__(128)
void midkernel(const float* __restrict__ x, const float* __restrict__ params,
               fp16* __restrict__ Zhi, fp16* __restrict__ Zlo)
{
    __shared__ float smem[12288];
    float* sX  = smem;
    float* sM  = smem + 2048;
    float* sST = smem + 6144;
    float* sO1 = smem + 10240;
    float* red = smem;

    const int ng = blockIdx.x;
    const int t  = threadIdx.x;
    const float* xb = x + (size_t)ng * (INP * EIN);
    const float* pb = params + (size_t)(ng >> 2) * PCOLS + (size_t)(ng & 3) * TOTALP;

    {
        const float4* x4 = (const float4*)xb;
        const float4* m4 = (const float4*)pb;
        const float4* s4 = (const float4*)(pb + 4096);
        ((float4*)sX)[t]       = x4[t];
        ((float4*)sX)[t + 128] = x4[t + 128];
        ((float4*)sX)[t + 256] = x4[t + 256];
        ((float4*)sX)[t + 384] = x4[t + 384];
        #pragma unroll
        for (int i = 0; i < 8; i++)
            ((float4*)sM)[t + 128 * i] = m4[t + 128 * i];
        #pragma unroll
        for (int i = 0; i < 8; i++) {
            int idx = t + 128 * i;
            float4 v = s4[idx];
            int qq = idx >> 3;
            int p4 = (idx & 7) << 2;
            sST[(p4 + 0) * 128 + qq] = v.x;
            sST[(p4 + 1) * 128 + qq] = v.y;
            sST[(p4 + 2) * 128 + qq] = v.z;
            sST[(p4 + 3) * 128 + qq] = v.w;
        }
    }
    __syncthreads();

    const int p0 = (t >> 3) << 1;
    const int og = (t & 7) << 3;
    ull acc1[2][4];
    #pragma unroll
    for (int i = 0; i < 2; i++)
        #pragma unroll
        for (int j = 0; j < 4; j++) acc1[i][j] = 0ull;

    #pragma unroll 4
    for (int cix = 0; cix < 64; cix++) {
        float xv0 = sX[p0 * 64 + cix];
        float xv1 = sX[(p0 + 1) * 64 + cix];
        ull x0 = pack2(xv0, xv0);
        ull x1 = pack2(xv1, xv1);
        const ulonglong2* mp = (const ulonglong2*)(sM + cix * 64 + og);
        ulonglong2 m0 = mp[0], m1 = mp[1];
        fma2(acc1[0][0], x0, m0.x); fma2(acc1[0][1], x0, m0.y);
        fma2(acc1[0][2], x0, m1.x); fma2(acc1[0][3], x0, m1.y);
        fma2(acc1[1][0], x1, m0.x); fma2(acc1[1][1], x1, m0.y);
        fma2(acc1[1][2], x1, m1.x); fma2(acc1[1][3], x1, m1.y);
    }
    float v1[2][8];
    float s1 = 0.f, q1 = 0.f;
    #pragma unroll
    for (int i = 0; i < 2; i++) {
        unpack2(acc1[i][0], v1[i][0], v1[i][1]); unpack2(acc1[i][1], v1[i][2], v1[i][3]);
        unpack2(acc1[i][2], v1[i][4], v1[i][5]); unpack2(acc1[i][3], v1[i][6], v1[i][7]);
        #pragma unroll
        for (int j = 0; j < 8; j++) { s1 += v1[i][j]; q1 += v1[i][j] * v1[i][j]; }
    }
    __syncthreads();
    blockReduce2_128(s1, q1, red);
    {
        float mean = s1 * (1.f / 2048.f);
        float var  = q1 * (1.f / 2048.f) - mean * mean;
        float rs   = rsqrtf(var + 1e-5f);
        #pragma unroll
        for (int i = 0; i < 2; i++)
            #pragma unroll
            for (int j = 0; j < 8; j++)
                sO1[(p0 + i) * 64 + og + j] = fmaxf((v1[i][j] - mean) * rs, 0.f);
    }
    __syncthreads();

    const int ty = t >> 3;
    const int tx = t & 7;
    ull acc2[8][4];
    #pragma unroll
    for (int i = 0; i < 8; i++)
        #pragma unroll
        for (int j = 0; j < 4; j++) acc2[i][j] = 0ull;

    #pragma unroll 2
    for (int p = 0; p < 32; p++) {
        const float4* stp = (const float4*)(sST + p * 128 + ty * 8);
        float4 sv0 = stp[0], sv1 = stp[1];
        const ulonglong2* op = (const ulonglong2*)(sO1 + p * 64 + tx * 8);
        ulonglong2 b0 = op[0], b1 = op[1];
        float svv[8] = {sv0.x, sv0.y, sv0.z, sv0.w, sv1.x, sv1.y, sv1.z, sv1.w};
        #pragma unroll
        for (int i = 0; i < 8; i++) {
            ull sp = pack2(svv[i], svv[i]);
            fma2(acc2[i][0], sp, b0.x); fma2(acc2[i][1], sp, b0.y);
            fma2(acc2[i][2], sp, b1.x); fma2(acc2[i][3], sp, b1.y);
        }
    }
    float v2[8][8];
    float s2 = 0.f, q2 = 0.f;
    #pragma unroll
    for (int i = 0; i < 8; i++) {
        unpack2(acc2[i][0], v2[i][0], v2[i][1]); unpack2(acc2[i][1], v2[i][2], v2[i][3]);
        unpack2(acc2[i][2], v2[i][4], v2[i][5]); unpack2(acc2[i][3], v2[i][6], v2[i][7]);
        #pragma unroll
        for (int j = 0; j < 8; j++) { s2 += v2[i][j]; q2 += v2[i][j] * v2[i][j]; }
    }
    blockReduce2_128(s2, q2, red);
    float mean2 = s2 * (1.f / 8192.f);
    float var2  = q2 * (1.f / 8192.f) - mean2 * mean2;
    float rs2   = rsqrtf(var2 + 1e-5f);

    const size_t zbase = (size_t)(ng >> 2) * PCOLS + (size_t)(ng & 3) * TOTALP;
    #pragma unroll
    for (int i = 0; i < 8; i++) {
        const int qrow = ty * 8 + i;
        fp16 h[8], l[8];
        #pragma unroll
        for (int j = 0; j < 8; j++) {
            float o = fmaxf((v2[i][j] - mean2) * rs2, 0.f);
            f2hiloH(o, h[j], l[j]);
        }
        size_t off = zbase + (size_t)qrow * 64 + tx * 8;
        *(uint4*)(Zhi + off) = make_uint4(hpk(h[0],h[1]), hpk(h[2],h[3]), hpk(h[4],h[5]), hpk(h[6],h[7]));
        *(uint4*)(Zlo + off) = make_uint4(hpk(l[0],l[1]), hpk(l[2],l[3]), hpk(l[4],l[5]), hpk(l[6],l[7]));
    }
}

// ---------------------------------------------------------------------------
__global__ void finalReduce(const float* __restrict__ part,
                            const float* __restrict__ query,
                            const float* __restrict__ bo,
                            float* __restrict__ out)
{
    int i = blockIdx.x * 256 + threadIdx.x;
    if (i >= NTOK * QDIM) return;
    float s = query[i] + bo[i & (QDIM - 1)];
    #pragma unroll
    for (int z = 0; z < SPLITK; z++)
        s += part[(size_t)z * NTOK * QDIM + i];
    out[i] = s;
}

// ---------------------------------------------------------------------------
extern "C" void kernel_launch(void* const* d_in, const int* in_sizes, int n_in,
                              void* d_out, int out_size)
{
    const float* x     = (const float*)d_in[0];
    const float* query = (const float*)d_in[1];
    const float* Wp    = (const float*)d_in[2];
    const float* bp    = (const float*)d_in[3];
    const float* Wo    = (const float*)d_in[4];
    const float* bo    = (const float*)d_in[5];
    float* out = (float*)d_out;

    float *pParams, *pPart;
    fp16 *pQh, *pQl, *pWpT, *pWoT, *pZh, *pZl;
    cudaGetSymbolAddress((void**)&pParams, g_params);
    cudaGetSymbolAddress((void**)&pPart, g_part);
    cudaGetSymbolAddress((void**)&pQh, g_qhi);
    cudaGetSymbolAddress((void**)&pQl, g_qlo);
    cudaGetSymbolAddress((void**)&pWpT, g_wpT);
    cudaGetSymbolAddress((void**)&pWoT, g_woT);
    cudaGetSymbolAddress((void**)&pZh, g_zhi);
    cudaGetSymbolAddress((void**)&pZl, g_zlo);

    static cudaStream_t s1 = nullptr, s2 = nullptr;
    static cudaEvent_t evRoot = nullptr, evWp = nullptr, evWo = nullptr;
    if (!s1) {
        cudaStreamCreateWithFlags(&s1, cudaStreamNonBlocking);
        cudaStreamCreateWithFlags(&s2, cudaStreamNonBlocking);
        cudaEventCreateWithFlags(&evRoot, cudaEventDisableTiming);
        cudaEventCreateWithFlags(&evWp, cudaEventDisableTiming);
        cudaEventCreateWithFlags(&evWo, cudaEventDisableTiming);
        cudaFuncSetAttribute(gemm_mma2, cudaFuncAttributeMaxDynamicSharedMemorySize, GSMEM2);
    }

    cudaEventRecord(evRoot, 0);
    cudaStreamWaitEvent(s1, evRoot, 0);
    cudaStreamWaitEvent(s2, evRoot, 0);

    convQf16<<<(NTOK * QDIM / 4 + 255) / 256, 256>>>(query, pQh, pQl);
    transConvF16<<<dim3(PCOLS / 32, QDIM / 32), dim3(32, 8), 0, s1>>>(Wp, pWpT, QDIM, PCOLS);
    transConvF16<<<dim3(QDIM / 32, PCOLS / 32), dim3(32, 8), 0, s2>>>(Wo, pWoT, PCOLS, QDIM);

    cudaEventRecord(evWp, s1);
    cudaStreamWaitEvent(0, evWp, 0);

    // GEMM1: params = q @ Wp + bp   (fp16 2-pass, K=256 -> 8 chunks of 32)
    gemm_mma2<<<dim3(PCOLS / 128, 29, 1), 256, GSMEM2>>>(
        pQh, pQl, pWpT, pParams, bp, NTOK, QDIM, QDIM, PCOLS, 8, 0);

    midkernel<<<NTOK * 4, 128>>>(x, pParams, pZh, pZl);

    cudaEventRecord(evWo, s2);
    cudaStreamWaitEvent(0, evWo, 0);

    // GEMM3: part[z] = Z[:, z*1024:(z+1)*1024] @ Wo-chunk  (fp16 2-pass)
    gemm_mma2<<<dim3(QDIM / 128, 29, SPLITK), 256, GSMEM2>>>(
        pZh, pZl, pWoT, pPart, nullptr,
        NTOK, PCOLS, PCOLS, QDIM, (PCOLS / SPLITK) / 32, (int)((size_t)NTOK * QDIM));

    finalReduce<<<(NTOK * QDIM + 255) / 256, 256>>>(pPart, query, bo, out);
}